// round 12
// baseline (speedup 1.0000x reference)
#include <cuda_runtime.h>
#include <cuda_bf16.h>
#include <cuda_fp16.h>
#include <math.h>
#include <stdint.h>

// ---------------- problem constants ----------------
#define MAXN 50000
#define MAXE 800000
#define MAXNE 100000
#define D 128

// ---------------- device scratch ----------------
__device__ __nv_bfloat16 g_Ahi[(size_t)(MAXNE + 128) * D];   // link: bf16 hi; trunk: HhB (fp16)
__device__ __nv_bfloat16 g_Alo[(size_t)(MAXNE + 128) * D];   // link: bf16 lo; trunk: x fp16
__device__ __half g_Hh [(size_t)(MAXN + 128) * D];           // fp16 trunk intermediate
__device__ float g_emb[(size_t)MAXN * D];
__device__ int   g_deg[MAXN];
__device__ int   g_rowptr[MAXN + 1];
__device__ int   g_cur[MAXN];
__device__ int   g_eidx[MAXE];
__device__ int   g_bsum[256];
// weights: slots 0..2 = W1..W3 fp16 hi/lo; slots 3..4 = P1,P2 bf16 hi/lo
__device__ __nv_bfloat16 g_Whi[5 * 16384];
__device__ __nv_bfloat16 g_Wlo[5 * 16384];

// ---------------- PTX helpers ----------------
__device__ __forceinline__ uint32_t smem_u32(const void* p) {
    uint32_t a;
    asm("{ .reg .u64 t; cvta.to.shared.u64 t, %1; cvt.u32.u64 %0, t; }" : "=r"(a) : "l"(p));
    return a;
}
__device__ __forceinline__ void ldsm4(uint32_t* r, uint32_t addr) {
    asm volatile("ldmatrix.sync.aligned.m8n8.x4.shared.b16 {%0,%1,%2,%3}, [%4];"
        : "=r"(r[0]), "=r"(r[1]), "=r"(r[2]), "=r"(r[3]) : "r"(addr));
}
__device__ __forceinline__ void mma_bf16(float* c, const uint32_t* a, const uint32_t* b) {
    asm volatile(
        "mma.sync.aligned.m16n8k16.row.col.f32.bf16.bf16.f32 "
        "{%0,%1,%2,%3}, {%4,%5,%6,%7}, {%8,%9}, {%0,%1,%2,%3};"
        : "+f"(c[0]), "+f"(c[1]), "+f"(c[2]), "+f"(c[3])
        : "r"(a[0]), "r"(a[1]), "r"(a[2]), "r"(a[3]), "r"(b[0]), "r"(b[1]));
}
__device__ __forceinline__ void mma_f16(float* c, const uint32_t* a, const uint32_t* b) {
    asm volatile(
        "mma.sync.aligned.m16n8k16.row.col.f32.f16.f16.f32 "
        "{%0,%1,%2,%3}, {%4,%5,%6,%7}, {%8,%9}, {%0,%1,%2,%3};"
        : "+f"(c[0]), "+f"(c[1]), "+f"(c[2]), "+f"(c[3])
        : "r"(a[0]), "r"(a[1]), "r"(a[2]), "r"(a[3]), "r"(b[0]), "r"(b[1]));
}
__device__ __forceinline__ void cp_async16(uint32_t saddr, const void* gptr) {
    asm volatile("cp.async.cg.shared.global [%0], [%1], 16;" :: "r"(saddr), "l"(gptr));
}
#define CP_COMMIT() asm volatile("cp.async.commit_group;" ::: "memory")
template <int NN> __device__ __forceinline__ void cp_wait() {
    asm volatile("cp.async.wait_group %0;" :: "n"(NN) : "memory");
}
__device__ __forceinline__ void split2b(float a, float b, uint32_t& hi, uint32_t& lo) {
    __nv_bfloat162 h = __floats2bfloat162_rn(a, b);
    float ra = a - __bfloat162float(h.x);
    float rb = b - __bfloat162float(h.y);
    __nv_bfloat162 l = __floats2bfloat162_rn(ra, rb);
    hi = *(uint32_t*)&h;
    lo = *(uint32_t*)&l;
}

// ---------------- CSR build kernels ----------------
__global__ void zero_int_kernel(int* p, int n) {
    for (int i = blockIdx.x * blockDim.x + threadIdx.x; i < n; i += gridDim.x * blockDim.x)
        p[i] = 0;
}
__global__ void hist_kernel(const int* __restrict__ dst, int E, int* __restrict__ deg) {
    for (int e = blockIdx.x * blockDim.x + threadIdx.x; e < E; e += gridDim.x * blockDim.x)
        atomicAdd(&deg[dst[e]], 1);
}
__global__ void scan1_kernel(const int* __restrict__ deg, int* __restrict__ rowptr,
                             int* __restrict__ bsum, int n) {
    __shared__ int wsum[32];
    int tid = threadIdx.x, lane = tid & 31, w = tid >> 5;
    int i = blockIdx.x * 1024 + tid;
    int v = (i < n) ? deg[i] : 0;
    int s = v;
    #pragma unroll
    for (int off = 1; off < 32; off <<= 1) {
        int t = __shfl_up_sync(0xFFFFFFFFu, s, off);
        if (lane >= off) s += t;
    }
    if (lane == 31) wsum[w] = s;
    __syncthreads();
    if (w == 0) {
        int ws = wsum[lane];
        #pragma unroll
        for (int off = 1; off < 32; off <<= 1) {
            int t = __shfl_up_sync(0xFFFFFFFFu, ws, off);
            if (lane >= off) ws += t;
        }
        wsum[lane] = ws;
    }
    __syncthreads();
    int prev = (w > 0) ? wsum[w - 1] : 0;
    int incl = prev + s;
    if (i < n) rowptr[i] = incl - v;
    if (tid == 1023) bsum[blockIdx.x] = incl;
}
__global__ void scan2_kernel(int* bsum, int nb) {
    int lane = threadIdx.x;
    int carry = 0;
    for (int base = 0; base < nb; base += 32) {
        int i = base + lane;
        int v = (i < nb) ? bsum[i] : 0;
        int s = v;
        #pragma unroll
        for (int off = 1; off < 32; off <<= 1) {
            int t = __shfl_up_sync(0xFFFFFFFFu, s, off);
            if (lane >= off) s += t;
        }
        if (i < nb) bsum[i] = carry + s - v;
        carry += __shfl_sync(0xFFFFFFFFu, s, 31);
    }
}
__global__ void scan3_kernel(const int* __restrict__ deg, int* __restrict__ rowptr,
                             int* __restrict__ cur, const int* __restrict__ bsum, int n) {
    int i = blockIdx.x * 1024 + threadIdx.x;
    if (i >= n) return;
    int val = rowptr[i] + bsum[blockIdx.x];
    rowptr[i] = val;
    cur[i] = val;
    if (i == n - 1) rowptr[n] = val + deg[n - 1];
}
__global__ void fill_csr_kernel(const int* __restrict__ src, const int* __restrict__ dst,
                                int E, int* __restrict__ cur, int* __restrict__ eidx) {
    for (int e = blockIdx.x * blockDim.x + threadIdx.x; e < E; e += gridDim.x * blockDim.x) {
        int d = dst[e];
        int p = atomicAdd(&cur[d], 1);
        eidx[p] = src[e];
    }
}

// ---------------- prep kernels ----------------
__global__ void prep_weights_kernel(const float* W1, const float* W2, const float* W3,
                                    const float* P1, const float* P2,
                                    __nv_bfloat16* hi, __nv_bfloat16* lo) {
    int idx = blockIdx.x * blockDim.x + threadIdx.x;
    if (idx >= 5 * 16384) return;
    int w = idx >> 14;
    int t = idx & 16383;
    int n = t >> 7;
    int k = t & 127;
    const float* Ws = (w == 0) ? W1 : (w == 1) ? W2 : (w == 2) ? W3 : (w == 3) ? P1 : P2;
    float v = Ws[(k << 7) | n];
    if (w < 3) {
        __half h = __float2half_rn(v);
        float rem = v - __half2float(h);
        ((__half*)hi)[idx] = h;
        ((__half*)lo)[idx] = __float2half_rn(rem);
    } else {
        __nv_bfloat16 h = __float2bfloat16(v);
        float rem = v - __bfloat162float(h);
        hi[idx] = h;
        lo[idx] = __float2bfloat16(rem);
    }
}
__global__ void xhalf_kernel(const float* __restrict__ x, __half* __restrict__ Ah, int N) {
    int n4 = N * 32;
    for (int idx = blockIdx.x * blockDim.x + threadIdx.x; idx < n4; idx += gridDim.x * blockDim.x) {
        float4 v = ((const float4*)x)[idx];
        __half2 h01 = __floats2half2_rn(v.x, v.y);
        __half2 h23 = __floats2half2_rn(v.z, v.w);
        uint2 p;
        p.x = *(uint32_t*)&h01; p.y = *(uint32_t*)&h23;
        *(uint2*)(Ah + (size_t)idx * 4) = p;
    }
}

// ================= fp16 2-pass GEMM (trunk), optional fused agg staging =================
#define ASTRIDE 136
#define TM 64
#define ABUF (TM * ASTRIDE)
#define WBUF (128 * ASTRIDE)
#define H_SA 0
#define H_SWH ABUF
#define H_SWL (ABUF + WBUF)
#define H_ELEMS (ABUF + 2 * WBUF)
#define H_SMEM_BYTES (H_ELEMS * 2 + 64)

// stagemode: 0 = cp.async dense fp16 rows from A
//            2 = fused aggregation: A_row[d] = relu(sum_{nbr} A[nbr] + bias)
__global__ void __launch_bounds__(256, 2)
gemm_f16_kernel(const __half* __restrict__ A,
                const int* __restrict__ rowptr, const int* __restrict__ eidx,
                const float* __restrict__ bias,
                const __half* __restrict__ Wt_hi, const __half* __restrict__ Wt_lo,
                __half* __restrict__ Ch, int M, int numTiles, int stagemode) {
    extern __shared__ __half smh[];
    uint32_t sbase = smem_u32(smh);
    int tid = threadIdx.x, wid = tid >> 5, lane = tid & 31;

    {
        const uint4* wh = (const uint4*)Wt_hi;
        const uint4* wl = (const uint4*)Wt_lo;
        for (int i = tid; i < 2048; i += 256) {
            int r = i >> 4, c = i & 15;
            *(uint4*)(smh + H_SWH + r * ASTRIDE + c * 8) = wh[i];
            *(uint4*)(smh + H_SWL + r * ASTRIDE + c * 8) = wl[i];
        }
    }

    float4 bv = make_float4(0.f, 0.f, 0.f, 0.f);
    if (stagemode == 2) bv = *(const float4*)(bias + (lane << 2));

    int mwid = wid >> 2;
    int nwid = wid & 3;
    int mrow0 = mwid << 5;
    int ncol0 = nwid << 5;

    uint32_t aRel = (uint32_t)(mrow0 + (lane & 15)) * (ASTRIDE * 2)
                  + (uint32_t)(((lane >> 4) << 3) * 2);
    uint32_t a0 = sbase + (H_SA * 2) + aRel;
    uint32_t a1 = a0 + 16 * (ASTRIDE * 2);

    uint32_t bN = (uint32_t)(ncol0 + ((lane >> 4) << 3) + (lane & 7));
    uint32_t bKB = (uint32_t)((((lane >> 3) & 1) << 3) * 2);
    uint32_t bHiBase = sbase + (H_SWH * 2) + bN * (ASTRIDE * 2) + bKB;
    uint32_t bLoBase = bHiBase + WBUF * 2;

    for (int t = blockIdx.x; t < numTiles; t += gridDim.x) {
        int row0 = t * TM;

        if (stagemode == 0) {
            #pragma unroll
            for (int it = 0; it < 4; it++) {
                int idx = it * 256 + tid;
                int r = idx >> 4, c = idx & 15;
                size_t goff = (size_t)(row0 + r) * D + c * 8;
                uint32_t soff = (r * ASTRIDE + c * 8) * 2;
                cp_async16(sbase + (H_SA * 2) + soff, A + goff);
            }
            CP_COMMIT();
            cp_wait<0>();
        } else {
            // fused aggregation staging: warp per dst row, 8 rows per warp
            for (int rr = 0; rr < 8; rr++) {
                int r = (wid << 3) + rr;             // 0..63
                int grow = row0 + r;
                float4 acc = make_float4(0.f, 0.f, 0.f, 0.f);
                if (grow < M) {
                    int beg = rowptr[grow], end = rowptr[grow + 1];
                    for (int j0 = beg; j0 < end; j0 += 32) {
                        int cnt = min(32, end - j0);
                        int e = (lane < cnt) ? eidx[j0 + lane] : 0;
                        for (int tt = 0; tt < cnt; tt++) {
                            int s = __shfl_sync(0xFFFFFFFFu, e, tt);
                            uint2 raw = *(const uint2*)(A + (size_t)s * D + (lane << 2));
                            __half2 h01 = *(__half2*)&raw.x;
                            __half2 h23 = *(__half2*)&raw.y;
                            float2 f01 = __half22float2(h01);
                            float2 f23 = __half22float2(h23);
                            acc.x += f01.x; acc.y += f01.y;
                            acc.z += f23.x; acc.w += f23.y;
                        }
                    }
                    acc.x = fmaxf(acc.x + bv.x, 0.f);
                    acc.y = fmaxf(acc.y + bv.y, 0.f);
                    acc.z = fmaxf(acc.z + bv.z, 0.f);
                    acc.w = fmaxf(acc.w + bv.w, 0.f);
                }
                __half2 h01 = __floats2half2_rn(acc.x, acc.y);
                __half2 h23 = __floats2half2_rn(acc.z, acc.w);
                uint2 p;
                p.x = *(uint32_t*)&h01; p.y = *(uint32_t*)&h23;
                *(uint2*)(smh + H_SA + r * ASTRIDE + (lane << 2)) = p;
            }
        }
        __syncthreads();

        float acc[2][4][4];
        #pragma unroll
        for (int mt = 0; mt < 2; mt++)
            #pragma unroll
            for (int nt = 0; nt < 4; nt++)
                #pragma unroll
                for (int q = 0; q < 4; q++) acc[mt][nt][q] = 0.0f;

        #pragma unroll
        for (int ks = 0; ks < 8; ks++) {
            uint32_t koffB = (uint32_t)(ks * 32);
            uint32_t af[2][4];
            ldsm4(af[0], a0 + koffB);
            ldsm4(af[1], a1 + koffB);
            uint32_t bh[4][2], bl[4][2];
            #pragma unroll
            for (int np = 0; np < 2; np++) {
                uint32_t r4[4];
                ldsm4(r4, bHiBase + (uint32_t)(np * 16 * ASTRIDE * 2) + koffB);
                bh[2 * np][0] = r4[0]; bh[2 * np][1] = r4[1];
                bh[2 * np + 1][0] = r4[2]; bh[2 * np + 1][1] = r4[3];
                ldsm4(r4, bLoBase + (uint32_t)(np * 16 * ASTRIDE * 2) + koffB);
                bl[2 * np][0] = r4[0]; bl[2 * np][1] = r4[1];
                bl[2 * np + 1][0] = r4[2]; bl[2 * np + 1][1] = r4[3];
            }
            #pragma unroll
            for (int mt = 0; mt < 2; mt++)
                #pragma unroll
                for (int nt = 0; nt < 4; nt++) {
                    mma_f16(acc[mt][nt], af[mt], bh[nt]);
                    mma_f16(acc[mt][nt], af[mt], bl[nt]);
                }
        }

        int cbase = ncol0 + ((lane & 3) << 1);
        int rbase = row0 + mrow0 + (lane >> 2);
        #pragma unroll
        for (int mt = 0; mt < 2; mt++) {
            #pragma unroll
            for (int half = 0; half < 2; half++) {
                int gr = rbase + mt * 16 + half * 8;
                if (gr >= M) continue;
                __half* cp = Ch + (size_t)gr * D;
                #pragma unroll
                for (int nt = 0; nt < 4; nt++) {
                    int col = cbase + nt * 8;
                    __half2 hp = __floats2half2_rn(acc[mt][nt][2 * half],
                                                   acc[mt][nt][2 * half + 1]);
                    *(uint32_t*)(cp + col) = *(uint32_t*)&hp;
                }
            }
        }
        __syncthreads();
    }
}

// ================= bf16 3-pass GEMM (link predictor) =================
#define B_SAHI 0
#define B_SALO ABUF
#define B_SWH (2 * ABUF)
#define B_SWL (2 * ABUF + WBUF)
#define B_ELEMS (2 * ABUF + 2 * WBUF)
#define B_SMEM_BYTES (B_ELEMS * 2 + (512 + 256 + 8) * 4)

__global__ void __launch_bounds__(256, 2)
gemm_bf16_kernel(const __nv_bfloat16* __restrict__ Ahi, const __nv_bfloat16* __restrict__ Alo,
                 const float* __restrict__ embf, const int* __restrict__ tedg,
                 const __nv_bfloat16* __restrict__ Wt_hi, const __nv_bfloat16* __restrict__ Wt_lo,
                 const float* __restrict__ bias,
                 __nv_bfloat16* __restrict__ OutHi, __nv_bfloat16* __restrict__ OutLo,
                 const float* __restrict__ P3, const float* __restrict__ pb3,
                 float* __restrict__ outF,
                 int M, int numTiles, int stagemode, int epimode) {
    extern __shared__ __nv_bfloat16 sm[];
    uint32_t sbase = smem_u32(sm);
    float* fpart = (float*)(sm + B_ELEMS);
    float* fP3 = fpart + 512;
    float* fpb3 = fP3 + 256;
    int tid = threadIdx.x, wid = tid >> 5, lane = tid & 31;

    {
        const uint4* wh = (const uint4*)Wt_hi;
        const uint4* wl = (const uint4*)Wt_lo;
        for (int i = tid; i < 2048; i += 256) {
            int r = i >> 4, c = i & 15;
            *(uint4*)(sm + B_SWH + r * ASTRIDE + c * 8) = wh[i];
            *(uint4*)(sm + B_SWL + r * ASTRIDE + c * 8) = wl[i];
        }
        if (epimode == 2) {
            fP3[tid] = P3[tid];
            if (tid < 2) fpb3[tid] = pb3[tid];
        }
    }

    int mwid = wid >> 2;
    int nwid = wid & 3;
    int mrow0 = mwid << 5;
    int ncol0 = nwid << 5;

    uint32_t aRel = (uint32_t)(mrow0 + (lane & 15)) * (ASTRIDE * 2)
                  + (uint32_t)(((lane >> 4) << 3) * 2);
    uint32_t aHi0 = sbase + (B_SAHI * 2) + aRel;
    uint32_t aHi1 = aHi0 + 16 * (ASTRIDE * 2);
    uint32_t aLo0 = aHi0 + ABUF * 2;
    uint32_t aLo1 = aHi1 + ABUF * 2;

    uint32_t bN = (uint32_t)(ncol0 + ((lane >> 4) << 3) + (lane & 7));
    uint32_t bKB = (uint32_t)((((lane >> 3) & 1) << 3) * 2);
    uint32_t bHiBase = sbase + (B_SWH * 2) + bN * (ASTRIDE * 2) + bKB;
    uint32_t bLoBase = bHiBase + WBUF * 2;

    for (int t = blockIdx.x; t < numTiles; t += gridDim.x) {
        int row0 = t * TM;

        if (stagemode == 0) {
            #pragma unroll
            for (int it = 0; it < 4; it++) {
                int idx = it * 256 + tid;
                int r = idx >> 4, c = idx & 15;
                size_t goff = (size_t)(row0 + r) * D + c * 8;
                uint32_t soff = (r * ASTRIDE + c * 8) * 2;
                cp_async16(sbase + (B_SAHI * 2) + soff, Ahi + goff);
                cp_async16(sbase + (B_SALO * 2) + soff, Alo + goff);
            }
            CP_COMMIT();
            cp_wait<0>();
        } else {
            #pragma unroll
            for (int it = 0; it < 8; it++) {
                int idx = it * 256 + tid;
                int r = idx >> 5;
                int c4 = idx & 31;
                int grow = row0 + r;
                float4 v;
                if (grow < M) {
                    int s = tedg[2 * grow];
                    int d = tedg[2 * grow + 1];
                    float4 a = *(const float4*)(embf + (size_t)s * D + c4 * 4);
                    float4 b = *(const float4*)(embf + (size_t)d * D + c4 * 4);
                    v = make_float4(a.x * b.x, a.y * b.y, a.z * b.z, a.w * b.w);
                } else {
                    v = make_float4(0.f, 0.f, 0.f, 0.f);
                }
                uint2 hp, lp;
                split2b(v.x, v.y, hp.x, lp.x);
                split2b(v.z, v.w, hp.y, lp.y);
                *(uint2*)(sm + B_SAHI + r * ASTRIDE + c4 * 4) = hp;
                *(uint2*)(sm + B_SALO + r * ASTRIDE + c4 * 4) = lp;
            }
        }
        __syncthreads();

        float acc[2][4][4];
        #pragma unroll
        for (int mt = 0; mt < 2; mt++)
            #pragma unroll
            for (int nt = 0; nt < 4; nt++)
                #pragma unroll
                for (int q = 0; q < 4; q++) acc[mt][nt][q] = 0.0f;

        #pragma unroll
        for (int ks = 0; ks < 8; ks++) {
            uint32_t koffB = (uint32_t)(ks * 32);
            uint32_t ah[2][4], al[2][4];
            ldsm4(ah[0], aHi0 + koffB);
            ldsm4(ah[1], aHi1 + koffB);
            ldsm4(al[0], aLo0 + koffB);
            ldsm4(al[1], aLo1 + koffB);
            uint32_t bh[4][2], bl[4][2];
            #pragma unroll
            for (int np = 0; np < 2; np++) {
                uint32_t r4[4];
                ldsm4(r4, bHiBase + (uint32_t)(np * 16 * ASTRIDE * 2) + koffB);
                bh[2 * np][0] = r4[0]; bh[2 * np][1] = r4[1];
                bh[2 * np + 1][0] = r4[2]; bh[2 * np + 1][1] = r4[3];
                ldsm4(r4, bLoBase + (uint32_t)(np * 16 * ASTRIDE * 2) + koffB);
                bl[2 * np][0] = r4[0]; bl[2 * np][1] = r4[1];
                bl[2 * np + 1][0] = r4[2]; bl[2 * np + 1][1] = r4[3];
            }
            #pragma unroll
            for (int mt = 0; mt < 2; mt++)
                #pragma unroll
                for (int nt = 0; nt < 4; nt++) {
                    mma_bf16(acc[mt][nt], ah[mt], bh[nt]);
                    mma_bf16(acc[mt][nt], ah[mt], bl[nt]);
                    mma_bf16(acc[mt][nt], al[mt], bh[nt]);
                }
        }

        int cbase = ncol0 + ((lane & 3) << 1);

        if (epimode == 2) {
            float q0a[4], q1a[4];
            #pragma unroll
            for (int mt = 0; mt < 2; mt++) {
                #pragma unroll
                for (int half = 0; half < 2; half++) {
                    float q0 = 0.f, q1 = 0.f;
                    #pragma unroll
                    for (int nt = 0; nt < 4; nt++) {
                        int col = cbase + nt * 8;
                        float z0 = fmaxf(acc[mt][nt][2 * half] + bias[col], 0.f);
                        float z1 = fmaxf(acc[mt][nt][2 * half + 1] + bias[col + 1], 0.f);
                        q0 += z0 * fP3[2 * col] + z1 * fP3[2 * (col + 1)];
                        q1 += z0 * fP3[2 * col + 1] + z1 * fP3[2 * (col + 1) + 1];
                    }
                    q0 += __shfl_xor_sync(0xFFFFFFFFu, q0, 1);
                    q0 += __shfl_xor_sync(0xFFFFFFFFu, q0, 2);
                    q1 += __shfl_xor_sync(0xFFFFFFFFu, q1, 1);
                    q1 += __shfl_xor_sync(0xFFFFFFFFu, q1, 2);
                    q0a[mt * 2 + half] = q0;
                    q1a[mt * 2 + half] = q1;
                    if (nwid != 0 && (lane & 3) == 0) {
                        int rl = mrow0 + mt * 16 + half * 8 + (lane >> 2);
                        fpart[rl * 8 + nwid * 2]     = q0;
                        fpart[rl * 8 + nwid * 2 + 1] = q1;
                    }
                }
            }
            __syncthreads();
            if (nwid == 0 && (lane & 3) == 0) {
                #pragma unroll
                for (int mt = 0; mt < 2; mt++) {
                    #pragma unroll
                    for (int half = 0; half < 2; half++) {
                        int rl = mrow0 + mt * 16 + half * 8 + (lane >> 2);
                        int gr = row0 + rl;
                        if (gr < M) {
                            float z0 = q0a[mt * 2 + half] + fpb3[0];
                            float z1 = q1a[mt * 2 + half] + fpb3[1];
                            #pragma unroll
                            for (int nw = 1; nw < 4; nw++) {
                                z0 += fpart[rl * 8 + nw * 2];
                                z1 += fpart[rl * 8 + nw * 2 + 1];
                            }
                            float nrm = fmaxf(sqrtf(z0 * z0 + z1 * z1), 1e-12f);
                            z0 /= nrm; z1 /= nrm;
                            float mm = fmaxf(z0, z1);
                            float lse = mm + logf(expf(z0 - mm) + expf(z1 - mm));
                            outF[2 * gr]     = z0 - lse;
                            outF[2 * gr + 1] = z1 - lse;
                        }
                    }
                }
            }
        } else {
            int rbase = row0 + mrow0 + (lane >> 2);
            #pragma unroll
            for (int mt = 0; mt < 2; mt++) {
                #pragma unroll
                for (int half = 0; half < 2; half++) {
                    int gr = rbase + mt * 16 + half * 8;
                    if (gr >= M) continue;
                    #pragma unroll
                    for (int nt = 0; nt < 4; nt++) {
                        int col = cbase + nt * 8;
                        float o0 = fmaxf(acc[mt][nt][2 * half] + bias[col], 0.f);
                        float o1 = fmaxf(acc[mt][nt][2 * half + 1] + bias[col + 1], 0.f);
                        uint32_t hp, lp;
                        split2b(o0, o1, hp, lp);
                        *(uint32_t*)(OutHi + (size_t)gr * D + col) = hp;
                        *(uint32_t*)(OutLo + (size_t)gr * D + col) = lp;
                    }
                }
            }
        }
        __syncthreads();
    }
}

// ---------------- standalone aggregation (final layer only): fp16 in, fp32 out ----------
__global__ void agg_kernel(const __half* __restrict__ H, const int* __restrict__ rowptr,
                           const int* __restrict__ eidx, const float* __restrict__ bias,
                           float* __restrict__ OutF, int N) {
    int gw = (blockIdx.x * blockDim.x + threadIdx.x) >> 5;
    int lane = threadIdx.x & 31;
    if (gw >= N) return;
    int beg = rowptr[gw], end = rowptr[gw + 1];
    float4 acc = make_float4(0.f, 0.f, 0.f, 0.f);
    for (int j0 = beg; j0 < end; j0 += 32) {
        int cnt = min(32, end - j0);
        int e = (lane < cnt) ? eidx[j0 + lane] : 0;
        for (int t = 0; t < cnt; t++) {
            int s = __shfl_sync(0xFFFFFFFFu, e, t);
            uint2 raw = *(const uint2*)(H + (size_t)s * D + (lane << 2));
            __half2 h01 = *(__half2*)&raw.x;
            __half2 h23 = *(__half2*)&raw.y;
            float2 f01 = __half22float2(h01);
            float2 f23 = __half22float2(h23);
            acc.x += f01.x; acc.y += f01.y; acc.z += f23.x; acc.w += f23.y;
        }
    }
    float4 bv = *(const float4*)(bias + (lane << 2));
    acc.x += bv.x; acc.y += bv.y; acc.z += bv.z; acc.w += bv.w;
    *(float4*)(OutF + (size_t)gw * D + (lane << 2)) = acc;
}

// ---------------- launch ----------------
extern "C" void kernel_launch(void* const* d_in, const int* in_sizes, int n_in,
                              void* d_out, int out_size) {
    const float* x    = (const float*)d_in[0];
    const int*   adj  = (const int*)d_in[1];
    const int*   tedg = (const int*)d_in[2];
    const float* W1 = (const float*)d_in[3];  const float* b1  = (const float*)d_in[4];
    const float* W2 = (const float*)d_in[5];  const float* b2  = (const float*)d_in[6];
    const float* W3 = (const float*)d_in[7];  const float* b3  = (const float*)d_in[8];
    const float* P1 = (const float*)d_in[9];  const float* pb1 = (const float*)d_in[10];
    const float* P2 = (const float*)d_in[11]; const float* pb2 = (const float*)d_in[12];
    const float* P3 = (const float*)d_in[13]; const float* pb3 = (const float*)d_in[14];
    float* out = (float*)d_out;

    int N  = in_sizes[0] / D;
    int E  = in_sizes[1] / 2;
    int NE = in_sizes[2] / 2;

    cudaFuncSetAttribute((const void*)gemm_f16_kernel,
                         cudaFuncAttributeMaxDynamicSharedMemorySize, H_SMEM_BYTES);
    cudaFuncSetAttribute((const void*)gemm_bf16_kernel,
                         cudaFuncAttributeMaxDynamicSharedMemorySize, B_SMEM_BYTES);

    __nv_bfloat16 *Ahi, *Alo, *Whi, *Wlo;
    __half* Hh;
    float* emb;
    int *deg, *rowptr, *cur, *eidx, *bsum;
    cudaGetSymbolAddress((void**)&Ahi, g_Ahi);
    cudaGetSymbolAddress((void**)&Alo, g_Alo);
    cudaGetSymbolAddress((void**)&Hh,  g_Hh);
    cudaGetSymbolAddress((void**)&emb, g_emb);
    cudaGetSymbolAddress((void**)&deg,    g_deg);
    cudaGetSymbolAddress((void**)&rowptr, g_rowptr);
    cudaGetSymbolAddress((void**)&cur,    g_cur);
    cudaGetSymbolAddress((void**)&eidx,   g_eidx);
    cudaGetSymbolAddress((void**)&bsum,   g_bsum);
    cudaGetSymbolAddress((void**)&Whi,  g_Whi);
    cudaGetSymbolAddress((void**)&Wlo,  g_Wlo);

    __half* Xh  = (__half*)Alo;                    // x as fp16 (dead once GEMM1 done... kept)
    __half* HhB = (__half*)Ahi;                    // second trunk H buffer
    const __half* Wh16 = (const __half*)Whi;
    const __half* Wl16 = (const __half*)Wlo;

    const int* src = adj;
    const int* dst = adj + E;

    int nScanBlk = (N + 1023) / 1024;
    int tilesN  = (N + TM - 1) / TM;
    int tilesNE = (NE + TM - 1) / TM;
    int gN  = tilesN  < 296 ? tilesN  : 296;
    int gNE = tilesNE < 296 ? tilesNE : 296;
    int aggBlk = (N * 32 + 255) / 256;

    // ---- prep + L1 GEMM early, CSR chain after ----
    prep_weights_kernel<<<(5 * 16384 + 255) / 256, 256>>>(W1, W2, W3, P1, P2, Whi, Wlo);
    xhalf_kernel<<<2048, 256>>>(x, Xh, N);
    zero_int_kernel<<<(N + 255) / 256, 256>>>(deg, N);
    gemm_f16_kernel<<<gN, 256, H_SMEM_BYTES>>>(Xh, nullptr, nullptr, nullptr,
        Wh16, Wl16, Hh, N, tilesN, 0);
    hist_kernel<<<(E + 255) / 256, 256>>>(dst, E, deg);
    scan1_kernel<<<nScanBlk, 1024>>>(deg, rowptr, bsum, N);
    scan2_kernel<<<1, 32>>>(bsum, nScanBlk);
    scan3_kernel<<<nScanBlk, 1024>>>(deg, rowptr, cur, bsum, N);
    fill_csr_kernel<<<(E + 255) / 256, 256>>>(src, dst, E, cur, eidx);

    // ---- trunk: fused agg+GEMM layers 2,3; standalone agg for layer 3 output ----
    gemm_f16_kernel<<<gN, 256, H_SMEM_BYTES>>>(Hh, rowptr, eidx, b1,
        Wh16 + 16384, Wl16 + 16384, HhB, N, tilesN, 2);
    gemm_f16_kernel<<<gN, 256, H_SMEM_BYTES>>>(HhB, rowptr, eidx, b2,
        Wh16 + 2 * 16384, Wl16 + 2 * 16384, Hh, N, tilesN, 2);
    agg_kernel<<<aggBlk, 256>>>(Hh, rowptr, eidx, b3, emb, N);

    // ---- link predictor (bf16 3-pass) ----
    gemm_bf16_kernel<<<gNE, 256, B_SMEM_BYTES>>>(nullptr, nullptr, emb, tedg,
        Whi + 3 * 16384, Wlo + 3 * 16384, pb1, Ahi, Alo, nullptr, nullptr, nullptr,
        NE, tilesNE, 1, 1);
    gemm_bf16_kernel<<<gNE, 256, B_SMEM_BYTES>>>(Ahi, Alo, nullptr, nullptr,
        Whi + 4 * 16384, Wlo + 4 * 16384, pb2, nullptr, nullptr, P3, pb3, out,
        NE, tilesNE, 0, 2);
}

// round 13
// speedup vs baseline: 1.2166x; 1.2166x over previous
#include <cuda_runtime.h>
#include <cuda_bf16.h>
#include <cuda_fp16.h>
#include <math.h>
#include <stdint.h>

// ---------------- problem constants ----------------
#define MAXN 50000
#define MAXE 800000
#define MAXNE 100000
#define D 128

// ---------------- device scratch ----------------
__device__ __nv_bfloat16 g_Ahi[(size_t)(MAXNE + 128) * D];
__device__ __nv_bfloat16 g_Alo[(size_t)(MAXNE + 128) * D];
__device__ __half g_Hh [(size_t)(MAXN + 128) * D];   // fp16 trunk intermediate
__device__ float g_emb[(size_t)MAXN * D];
__device__ int   g_deg[MAXN];
__device__ int   g_rowptr[MAXN + 1];
__device__ int   g_cur[MAXN];
__device__ int   g_eidx[MAXE];
__device__ int   g_bsum[256];
// weights: slots 0..2 = W1..W3 fp16 hi/lo; slots 3..4 = P1,P2 bf16 hi/lo
__device__ __nv_bfloat16 g_Whi[5 * 16384];
__device__ __nv_bfloat16 g_Wlo[5 * 16384];

// ---------------- PTX helpers ----------------
__device__ __forceinline__ uint32_t smem_u32(const void* p) {
    uint32_t a;
    asm("{ .reg .u64 t; cvta.to.shared.u64 t, %1; cvt.u32.u64 %0, t; }" : "=r"(a) : "l"(p));
    return a;
}
__device__ __forceinline__ void ldsm4(uint32_t* r, uint32_t addr) {
    asm volatile("ldmatrix.sync.aligned.m8n8.x4.shared.b16 {%0,%1,%2,%3}, [%4];"
        : "=r"(r[0]), "=r"(r[1]), "=r"(r[2]), "=r"(r[3]) : "r"(addr));
}
__device__ __forceinline__ void mma_bf16(float* c, const uint32_t* a, const uint32_t* b) {
    asm volatile(
        "mma.sync.aligned.m16n8k16.row.col.f32.bf16.bf16.f32 "
        "{%0,%1,%2,%3}, {%4,%5,%6,%7}, {%8,%9}, {%0,%1,%2,%3};"
        : "+f"(c[0]), "+f"(c[1]), "+f"(c[2]), "+f"(c[3])
        : "r"(a[0]), "r"(a[1]), "r"(a[2]), "r"(a[3]), "r"(b[0]), "r"(b[1]));
}
__device__ __forceinline__ void mma_f16(float* c, const uint32_t* a, const uint32_t* b) {
    asm volatile(
        "mma.sync.aligned.m16n8k16.row.col.f32.f16.f16.f32 "
        "{%0,%1,%2,%3}, {%4,%5,%6,%7}, {%8,%9}, {%0,%1,%2,%3};"
        : "+f"(c[0]), "+f"(c[1]), "+f"(c[2]), "+f"(c[3])
        : "r"(a[0]), "r"(a[1]), "r"(a[2]), "r"(a[3]), "r"(b[0]), "r"(b[1]));
}
__device__ __forceinline__ void cp_async16(uint32_t saddr, const void* gptr) {
    asm volatile("cp.async.cg.shared.global [%0], [%1], 16;" :: "r"(saddr), "l"(gptr));
}
#define CP_COMMIT() asm volatile("cp.async.commit_group;" ::: "memory")
template <int NN> __device__ __forceinline__ void cp_wait() {
    asm volatile("cp.async.wait_group %0;" :: "n"(NN) : "memory");
}
__device__ __forceinline__ void split2b(float a, float b, uint32_t& hi, uint32_t& lo) {
    __nv_bfloat162 h = __floats2bfloat162_rn(a, b);
    float ra = a - __bfloat162float(h.x);
    float rb = b - __bfloat162float(h.y);
    __nv_bfloat162 l = __floats2bfloat162_rn(ra, rb);
    hi = *(uint32_t*)&h;
    lo = *(uint32_t*)&l;
}

// ---------------- CSR build kernels ----------------
__global__ void zero_int_kernel(int* p, int n) {
    for (int i = blockIdx.x * blockDim.x + threadIdx.x; i < n; i += gridDim.x * blockDim.x)
        p[i] = 0;
}
__global__ void hist_kernel(const int* __restrict__ dst, int E, int* __restrict__ deg) {
    for (int e = blockIdx.x * blockDim.x + threadIdx.x; e < E; e += gridDim.x * blockDim.x)
        atomicAdd(&deg[dst[e]], 1);
}
__global__ void scan1_kernel(const int* __restrict__ deg, int* __restrict__ rowptr,
                             int* __restrict__ bsum, int n) {
    __shared__ int wsum[32];
    int tid = threadIdx.x, lane = tid & 31, w = tid >> 5;
    int i = blockIdx.x * 1024 + tid;
    int v = (i < n) ? deg[i] : 0;
    int s = v;
    #pragma unroll
    for (int off = 1; off < 32; off <<= 1) {
        int t = __shfl_up_sync(0xFFFFFFFFu, s, off);
        if (lane >= off) s += t;
    }
    if (lane == 31) wsum[w] = s;
    __syncthreads();
    if (w == 0) {
        int ws = wsum[lane];
        #pragma unroll
        for (int off = 1; off < 32; off <<= 1) {
            int t = __shfl_up_sync(0xFFFFFFFFu, ws, off);
            if (lane >= off) ws += t;
        }
        wsum[lane] = ws;
    }
    __syncthreads();
    int prev = (w > 0) ? wsum[w - 1] : 0;
    int incl = prev + s;
    if (i < n) rowptr[i] = incl - v;
    if (tid == 1023) bsum[blockIdx.x] = incl;
}
__global__ void scan2_kernel(int* bsum, int nb) {
    int lane = threadIdx.x;
    int carry = 0;
    for (int base = 0; base < nb; base += 32) {
        int i = base + lane;
        int v = (i < nb) ? bsum[i] : 0;
        int s = v;
        #pragma unroll
        for (int off = 1; off < 32; off <<= 1) {
            int t = __shfl_up_sync(0xFFFFFFFFu, s, off);
            if (lane >= off) s += t;
        }
        if (i < nb) bsum[i] = carry + s - v;
        carry += __shfl_sync(0xFFFFFFFFu, s, 31);
    }
}
__global__ void scan3_kernel(const int* __restrict__ deg, int* __restrict__ rowptr,
                             int* __restrict__ cur, const int* __restrict__ bsum, int n) {
    int i = blockIdx.x * 1024 + threadIdx.x;
    if (i >= n) return;
    int val = rowptr[i] + bsum[blockIdx.x];
    rowptr[i] = val;
    cur[i] = val;
    if (i == n - 1) rowptr[n] = val + deg[n - 1];
}
__global__ void fill_csr_kernel(const int* __restrict__ src, const int* __restrict__ dst,
                                int E, int* __restrict__ cur, int* __restrict__ eidx) {
    for (int e = blockIdx.x * blockDim.x + threadIdx.x; e < E; e += gridDim.x * blockDim.x) {
        int d = dst[e];
        int p = atomicAdd(&cur[d], 1);
        eidx[p] = src[e];
    }
}

// ---------------- prep kernels ----------------
__global__ void prep_weights_kernel(const float* W1, const float* W2, const float* W3,
                                    const float* P1, const float* P2,
                                    __nv_bfloat16* hi, __nv_bfloat16* lo) {
    int idx = blockIdx.x * blockDim.x + threadIdx.x;
    if (idx >= 5 * 16384) return;
    int w = idx >> 14;
    int t = idx & 16383;
    int n = t >> 7;
    int k = t & 127;
    const float* Ws = (w == 0) ? W1 : (w == 1) ? W2 : (w == 2) ? W3 : (w == 3) ? P1 : P2;
    float v = Ws[(k << 7) | n];
    if (w < 3) {
        __half h = __float2half_rn(v);
        float rem = v - __half2float(h);
        ((__half*)hi)[idx] = h;
        ((__half*)lo)[idx] = __float2half_rn(rem);
    } else {
        __nv_bfloat16 h = __float2bfloat16(v);
        float rem = v - __bfloat162float(h);
        hi[idx] = h;
        lo[idx] = __float2bfloat16(rem);
    }
}
__global__ void xhalf_kernel(const float* __restrict__ x, __half* __restrict__ Ah, int N) {
    int n4 = N * 32;
    for (int idx = blockIdx.x * blockDim.x + threadIdx.x; idx < n4; idx += gridDim.x * blockDim.x) {
        float4 v = ((const float4*)x)[idx];
        __half2 h01 = __floats2half2_rn(v.x, v.y);
        __half2 h23 = __floats2half2_rn(v.z, v.w);
        uint2 p;
        p.x = *(uint32_t*)&h01; p.y = *(uint32_t*)&h23;
        *(uint2*)(Ah + (size_t)idx * 4) = p;
    }
}

// ================= fp16 2-pass GEMM (trunk): Ch = A @ (Wh + Wl), fp16 out =================
#define ASTRIDE 136
#define TM 64
#define ABUF (TM * ASTRIDE)
#define WBUF (128 * ASTRIDE)
#define H_SA 0
#define H_SWH ABUF
#define H_SWL (ABUF + WBUF)
#define H_ELEMS (ABUF + 2 * WBUF)
#define H_SMEM_BYTES (H_ELEMS * 2 + 64)

__global__ void __launch_bounds__(256, 2)
gemm_f16_kernel(const __half* __restrict__ A,
                const __half* __restrict__ Wt_hi, const __half* __restrict__ Wt_lo,
                __half* __restrict__ Ch, int M, int numTiles) {
    extern __shared__ __half smh[];
    uint32_t sbase = smem_u32(smh);
    int tid = threadIdx.x, wid = tid >> 5, lane = tid & 31;

    {
        const uint4* wh = (const uint4*)Wt_hi;
        const uint4* wl = (const uint4*)Wt_lo;
        for (int i = tid; i < 2048; i += 256) {
            int r = i >> 4, c = i & 15;
            *(uint4*)(smh + H_SWH + r * ASTRIDE + c * 8) = wh[i];
            *(uint4*)(smh + H_SWL + r * ASTRIDE + c * 8) = wl[i];
        }
    }

    int mwid = wid >> 2;
    int nwid = wid & 3;
    int mrow0 = mwid << 5;
    int ncol0 = nwid << 5;

    uint32_t aRel = (uint32_t)(mrow0 + (lane & 15)) * (ASTRIDE * 2)
                  + (uint32_t)(((lane >> 4) << 3) * 2);
    uint32_t a0 = sbase + (H_SA * 2) + aRel;
    uint32_t a1 = a0 + 16 * (ASTRIDE * 2);

    uint32_t bN = (uint32_t)(ncol0 + ((lane >> 4) << 3) + (lane & 7));
    uint32_t bKB = (uint32_t)((((lane >> 3) & 1) << 3) * 2);
    uint32_t bHiBase = sbase + (H_SWH * 2) + bN * (ASTRIDE * 2) + bKB;
    uint32_t bLoBase = bHiBase + WBUF * 2;

    for (int t = blockIdx.x; t < numTiles; t += gridDim.x) {
        int row0 = t * TM;
        #pragma unroll
        for (int it = 0; it < 4; it++) {
            int idx = it * 256 + tid;
            int r = idx >> 4, c = idx & 15;
            size_t goff = (size_t)(row0 + r) * D + c * 8;
            uint32_t soff = (r * ASTRIDE + c * 8) * 2;
            cp_async16(sbase + (H_SA * 2) + soff, A + goff);
        }
        CP_COMMIT();
        cp_wait<0>();
        __syncthreads();

        float acc[2][4][4];
        #pragma unroll
        for (int mt = 0; mt < 2; mt++)
            #pragma unroll
            for (int nt = 0; nt < 4; nt++)
                #pragma unroll
                for (int q = 0; q < 4; q++) acc[mt][nt][q] = 0.0f;

        #pragma unroll
        for (int ks = 0; ks < 8; ks++) {
            uint32_t koffB = (uint32_t)(ks * 32);
            uint32_t af[2][4];
            ldsm4(af[0], a0 + koffB);
            ldsm4(af[1], a1 + koffB);
            uint32_t bh[4][2], bl[4][2];
            #pragma unroll
            for (int np = 0; np < 2; np++) {
                uint32_t r4[4];
                ldsm4(r4, bHiBase + (uint32_t)(np * 16 * ASTRIDE * 2) + koffB);
                bh[2 * np][0] = r4[0]; bh[2 * np][1] = r4[1];
                bh[2 * np + 1][0] = r4[2]; bh[2 * np + 1][1] = r4[3];
                ldsm4(r4, bLoBase + (uint32_t)(np * 16 * ASTRIDE * 2) + koffB);
                bl[2 * np][0] = r4[0]; bl[2 * np][1] = r4[1];
                bl[2 * np + 1][0] = r4[2]; bl[2 * np + 1][1] = r4[3];
            }
            #pragma unroll
            for (int mt = 0; mt < 2; mt++)
                #pragma unroll
                for (int nt = 0; nt < 4; nt++) {
                    mma_f16(acc[mt][nt], af[mt], bh[nt]);
                    mma_f16(acc[mt][nt], af[mt], bl[nt]);
                }
        }

        int cbase = ncol0 + ((lane & 3) << 1);
        int rbase = row0 + mrow0 + (lane >> 2);
        #pragma unroll
        for (int mt = 0; mt < 2; mt++) {
            #pragma unroll
            for (int half = 0; half < 2; half++) {
                int gr = rbase + mt * 16 + half * 8;
                if (gr >= M) continue;
                __half* cp = Ch + (size_t)gr * D;
                #pragma unroll
                for (int nt = 0; nt < 4; nt++) {
                    int col = cbase + nt * 8;
                    __half2 hp = __floats2half2_rn(acc[mt][nt][2 * half],
                                                   acc[mt][nt][2 * half + 1]);
                    *(uint32_t*)(cp + col) = *(uint32_t*)&hp;
                }
            }
        }
        __syncthreads();
    }
}

// ================= bf16 3-pass GEMM (link predictor) =================
#define B_SAHI 0
#define B_SALO ABUF
#define B_SWH (2 * ABUF)
#define B_SWL (2 * ABUF + WBUF)
#define B_ELEMS (2 * ABUF + 2 * WBUF)
#define B_SMEM_BYTES (B_ELEMS * 2 + (512 + 256 + 8) * 4)

__global__ void __launch_bounds__(256, 2)
gemm_bf16_kernel(const __nv_bfloat16* __restrict__ Ahi, const __nv_bfloat16* __restrict__ Alo,
                 const float* __restrict__ embf, const int* __restrict__ tedg,
                 const __nv_bfloat16* __restrict__ Wt_hi, const __nv_bfloat16* __restrict__ Wt_lo,
                 const float* __restrict__ bias,
                 __nv_bfloat16* __restrict__ OutHi, __nv_bfloat16* __restrict__ OutLo,
                 const float* __restrict__ P3, const float* __restrict__ pb3,
                 float* __restrict__ outF,
                 int M, int numTiles, int stagemode, int epimode) {
    extern __shared__ __nv_bfloat16 sm[];
    uint32_t sbase = smem_u32(sm);
    float* fpart = (float*)(sm + B_ELEMS);
    float* fP3 = fpart + 512;
    float* fpb3 = fP3 + 256;
    int tid = threadIdx.x, wid = tid >> 5, lane = tid & 31;

    {
        const uint4* wh = (const uint4*)Wt_hi;
        const uint4* wl = (const uint4*)Wt_lo;
        for (int i = tid; i < 2048; i += 256) {
            int r = i >> 4, c = i & 15;
            *(uint4*)(sm + B_SWH + r * ASTRIDE + c * 8) = wh[i];
            *(uint4*)(sm + B_SWL + r * ASTRIDE + c * 8) = wl[i];
        }
        if (epimode == 2) {
            fP3[tid] = P3[tid];
            if (tid < 2) fpb3[tid] = pb3[tid];
        }
    }

    int mwid = wid >> 2;
    int nwid = wid & 3;
    int mrow0 = mwid << 5;
    int ncol0 = nwid << 5;

    uint32_t aRel = (uint32_t)(mrow0 + (lane & 15)) * (ASTRIDE * 2)
                  + (uint32_t)(((lane >> 4) << 3) * 2);
    uint32_t aHi0 = sbase + (B_SAHI * 2) + aRel;
    uint32_t aHi1 = aHi0 + 16 * (ASTRIDE * 2);
    uint32_t aLo0 = aHi0 + ABUF * 2;
    uint32_t aLo1 = aHi1 + ABUF * 2;

    uint32_t bN = (uint32_t)(ncol0 + ((lane >> 4) << 3) + (lane & 7));
    uint32_t bKB = (uint32_t)((((lane >> 3) & 1) << 3) * 2);
    uint32_t bHiBase = sbase + (B_SWH * 2) + bN * (ASTRIDE * 2) + bKB;
    uint32_t bLoBase = bHiBase + WBUF * 2;

    for (int t = blockIdx.x; t < numTiles; t += gridDim.x) {
        int row0 = t * TM;

        if (stagemode == 0) {
            #pragma unroll
            for (int it = 0; it < 4; it++) {
                int idx = it * 256 + tid;
                int r = idx >> 4, c = idx & 15;
                size_t goff = (size_t)(row0 + r) * D + c * 8;
                uint32_t soff = (r * ASTRIDE + c * 8) * 2;
                cp_async16(sbase + (B_SAHI * 2) + soff, Ahi + goff);
                cp_async16(sbase + (B_SALO * 2) + soff, Alo + goff);
            }
            CP_COMMIT();
            cp_wait<0>();
        } else {
            #pragma unroll
            for (int it = 0; it < 8; it++) {
                int idx = it * 256 + tid;
                int r = idx >> 5;
                int c4 = idx & 31;
                int grow = row0 + r;
                float4 v;
                if (grow < M) {
                    int s = tedg[2 * grow];
                    int d = tedg[2 * grow + 1];
                    float4 a = *(const float4*)(embf + (size_t)s * D + c4 * 4);
                    float4 b = *(const float4*)(embf + (size_t)d * D + c4 * 4);
                    v = make_float4(a.x * b.x, a.y * b.y, a.z * b.z, a.w * b.w);
                } else {
                    v = make_float4(0.f, 0.f, 0.f, 0.f);
                }
                uint2 hp, lp;
                split2b(v.x, v.y, hp.x, lp.x);
                split2b(v.z, v.w, hp.y, lp.y);
                *(uint2*)(sm + B_SAHI + r * ASTRIDE + c4 * 4) = hp;
                *(uint2*)(sm + B_SALO + r * ASTRIDE + c4 * 4) = lp;
            }
        }
        __syncthreads();

        float acc[2][4][4];
        #pragma unroll
        for (int mt = 0; mt < 2; mt++)
            #pragma unroll
            for (int nt = 0; nt < 4; nt++)
                #pragma unroll
                for (int q = 0; q < 4; q++) acc[mt][nt][q] = 0.0f;

        #pragma unroll
        for (int ks = 0; ks < 8; ks++) {
            uint32_t koffB = (uint32_t)(ks * 32);
            uint32_t ah[2][4], al[2][4];
            ldsm4(ah[0], aHi0 + koffB);
            ldsm4(ah[1], aHi1 + koffB);
            ldsm4(al[0], aLo0 + koffB);
            ldsm4(al[1], aLo1 + koffB);
            uint32_t bh[4][2], bl[4][2];
            #pragma unroll
            for (int np = 0; np < 2; np++) {
                uint32_t r4[4];
                ldsm4(r4, bHiBase + (uint32_t)(np * 16 * ASTRIDE * 2) + koffB);
                bh[2 * np][0] = r4[0]; bh[2 * np][1] = r4[1];
                bh[2 * np + 1][0] = r4[2]; bh[2 * np + 1][1] = r4[3];
                ldsm4(r4, bLoBase + (uint32_t)(np * 16 * ASTRIDE * 2) + koffB);
                bl[2 * np][0] = r4[0]; bl[2 * np][1] = r4[1];
                bl[2 * np + 1][0] = r4[2]; bl[2 * np + 1][1] = r4[3];
            }
            #pragma unroll
            for (int mt = 0; mt < 2; mt++)
                #pragma unroll
                for (int nt = 0; nt < 4; nt++) {
                    mma_bf16(acc[mt][nt], ah[mt], bh[nt]);
                    mma_bf16(acc[mt][nt], ah[mt], bl[nt]);
                    mma_bf16(acc[mt][nt], al[mt], bh[nt]);
                }
        }

        int cbase = ncol0 + ((lane & 3) << 1);

        if (epimode == 2) {
            float q0a[4], q1a[4];
            #pragma unroll
            for (int mt = 0; mt < 2; mt++) {
                #pragma unroll
                for (int half = 0; half < 2; half++) {
                    float q0 = 0.f, q1 = 0.f;
                    #pragma unroll
                    for (int nt = 0; nt < 4; nt++) {
                        int col = cbase + nt * 8;
                        float z0 = fmaxf(acc[mt][nt][2 * half] + bias[col], 0.f);
                        float z1 = fmaxf(acc[mt][nt][2 * half + 1] + bias[col + 1], 0.f);
                        q0 += z0 * fP3[2 * col] + z1 * fP3[2 * (col + 1)];
                        q1 += z0 * fP3[2 * col + 1] + z1 * fP3[2 * (col + 1) + 1];
                    }
                    q0 += __shfl_xor_sync(0xFFFFFFFFu, q0, 1);
                    q0 += __shfl_xor_sync(0xFFFFFFFFu, q0, 2);
                    q1 += __shfl_xor_sync(0xFFFFFFFFu, q1, 1);
                    q1 += __shfl_xor_sync(0xFFFFFFFFu, q1, 2);
                    q0a[mt * 2 + half] = q0;
                    q1a[mt * 2 + half] = q1;
                    if (nwid != 0 && (lane & 3) == 0) {
                        int rl = mrow0 + mt * 16 + half * 8 + (lane >> 2);
                        fpart[rl * 8 + nwid * 2]     = q0;
                        fpart[rl * 8 + nwid * 2 + 1] = q1;
                    }
                }
            }
            __syncthreads();
            if (nwid == 0 && (lane & 3) == 0) {
                #pragma unroll
                for (int mt = 0; mt < 2; mt++) {
                    #pragma unroll
                    for (int half = 0; half < 2; half++) {
                        int rl = mrow0 + mt * 16 + half * 8 + (lane >> 2);
                        int gr = row0 + rl;
                        if (gr < M) {
                            float z0 = q0a[mt * 2 + half] + fpb3[0];
                            float z1 = q1a[mt * 2 + half] + fpb3[1];
                            #pragma unroll
                            for (int nw = 1; nw < 4; nw++) {
                                z0 += fpart[rl * 8 + nw * 2];
                                z1 += fpart[rl * 8 + nw * 2 + 1];
                            }
                            float nrm = fmaxf(sqrtf(z0 * z0 + z1 * z1), 1e-12f);
                            z0 /= nrm; z1 /= nrm;
                            float mm = fmaxf(z0, z1);
                            float lse = mm + logf(expf(z0 - mm) + expf(z1 - mm));
                            outF[2 * gr]     = z0 - lse;
                            outF[2 * gr + 1] = z1 - lse;
                        }
                    }
                }
            }
        } else {
            int rbase = row0 + mrow0 + (lane >> 2);
            #pragma unroll
            for (int mt = 0; mt < 2; mt++) {
                #pragma unroll
                for (int half = 0; half < 2; half++) {
                    int gr = rbase + mt * 16 + half * 8;
                    if (gr >= M) continue;
                    #pragma unroll
                    for (int nt = 0; nt < 4; nt++) {
                        int col = cbase + nt * 8;
                        float o0 = fmaxf(acc[mt][nt][2 * half] + bias[col], 0.f);
                        float o1 = fmaxf(acc[mt][nt][2 * half + 1] + bias[col + 1], 0.f);
                        uint32_t hp, lp;
                        split2b(o0, o1, hp, lp);
                        *(uint32_t*)(OutHi + (size_t)gr * D + col) = hp;
                        *(uint32_t*)(OutLo + (size_t)gr * D + col) = lp;
                    }
                }
            }
        }
        __syncthreads();
    }
}

// ---------------- aggregation: warp-per-dst, uniform-load index broadcast ----------------
// fp16 gather; out fp16 (outmode 0, +relu) or fp32 (outmode 1)
__global__ void agg_kernel(const __half* __restrict__ H, const int* __restrict__ rowptr,
                           const int* __restrict__ eidx, const float* __restrict__ bias,
                           __half* __restrict__ OutH, float* __restrict__ OutF,
                           int relu, int outmode, int N) {
    int gw = (blockIdx.x * blockDim.x + threadIdx.x) >> 5;
    int lane = threadIdx.x & 31;
    if (gw >= N) return;
    int beg = rowptr[gw], end = rowptr[gw + 1];
    float4 acc = make_float4(0.f, 0.f, 0.f, 0.f);
    int coff = lane << 2;
    // uniform index loads (hardware broadcast) + unroll-4 for MLP; no shfl chain
    int j = beg;
    #pragma unroll 1
    for (; j + 4 <= end; j += 4) {
        int s0 = eidx[j];
        int s1 = eidx[j + 1];
        int s2 = eidx[j + 2];
        int s3 = eidx[j + 3];
        uint2 r0 = *(const uint2*)(H + (size_t)s0 * D + coff);
        uint2 r1 = *(const uint2*)(H + (size_t)s1 * D + coff);
        uint2 r2 = *(const uint2*)(H + (size_t)s2 * D + coff);
        uint2 r3 = *(const uint2*)(H + (size_t)s3 * D + coff);
        float2 a0 = __half22float2(*(__half2*)&r0.x), b0 = __half22float2(*(__half2*)&r0.y);
        float2 a1 = __half22float2(*(__half2*)&r1.x), b1 = __half22float2(*(__half2*)&r1.y);
        float2 a2 = __half22float2(*(__half2*)&r2.x), b2 = __half22float2(*(__half2*)&r2.y);
        float2 a3 = __half22float2(*(__half2*)&r3.x), b3 = __half22float2(*(__half2*)&r3.y);
        acc.x += a0.x; acc.y += a0.y; acc.z += b0.x; acc.w += b0.y;
        acc.x += a1.x; acc.y += a1.y; acc.z += b1.x; acc.w += b1.y;
        acc.x += a2.x; acc.y += a2.y; acc.z += b2.x; acc.w += b2.y;
        acc.x += a3.x; acc.y += a3.y; acc.z += b3.x; acc.w += b3.y;
    }
    for (; j < end; j++) {
        int s = eidx[j];
        uint2 raw = *(const uint2*)(H + (size_t)s * D + coff);
        float2 f01 = __half22float2(*(__half2*)&raw.x);
        float2 f23 = __half22float2(*(__half2*)&raw.y);
        acc.x += f01.x; acc.y += f01.y; acc.z += f23.x; acc.w += f23.y;
    }
    float4 bv = *(const float4*)(bias + coff);
    acc.x += bv.x; acc.y += bv.y; acc.z += bv.z; acc.w += bv.w;
    if (relu) {
        acc.x = fmaxf(acc.x, 0.f); acc.y = fmaxf(acc.y, 0.f);
        acc.z = fmaxf(acc.z, 0.f); acc.w = fmaxf(acc.w, 0.f);
    }
    if (outmode == 0) {
        __half2 h01 = __floats2half2_rn(acc.x, acc.y);
        __half2 h23 = __floats2half2_rn(acc.z, acc.w);
        uint2 p;
        p.x = *(uint32_t*)&h01; p.y = *(uint32_t*)&h23;
        *(uint2*)(OutH + (size_t)gw * D + coff) = p;
    } else {
        *(float4*)(OutF + (size_t)gw * D + coff) = acc;
    }
}

// ---------------- launch ----------------
extern "C" void kernel_launch(void* const* d_in, const int* in_sizes, int n_in,
                              void* d_out, int out_size) {
    const float* x    = (const float*)d_in[0];
    const int*   adj  = (const int*)d_in[1];
    const int*   tedg = (const int*)d_in[2];
    const float* W1 = (const float*)d_in[3];  const float* b1  = (const float*)d_in[4];
    const float* W2 = (const float*)d_in[5];  const float* b2  = (const float*)d_in[6];
    const float* W3 = (const float*)d_in[7];  const float* b3  = (const float*)d_in[8];
    const float* P1 = (const float*)d_in[9];  const float* pb1 = (const float*)d_in[10];
    const float* P2 = (const float*)d_in[11]; const float* pb2 = (const float*)d_in[12];
    const float* P3 = (const float*)d_in[13]; const float* pb3 = (const float*)d_in[14];
    float* out = (float*)d_out;

    int N  = in_sizes[0] / D;
    int E  = in_sizes[1] / 2;
    int NE = in_sizes[2] / 2;

    cudaFuncSetAttribute((const void*)gemm_f16_kernel,
                         cudaFuncAttributeMaxDynamicSharedMemorySize, H_SMEM_BYTES);
    cudaFuncSetAttribute((const void*)gemm_bf16_kernel,
                         cudaFuncAttributeMaxDynamicSharedMemorySize, B_SMEM_BYTES);

    __nv_bfloat16 *Ahi, *Alo, *Whi, *Wlo;
    __half* Hh;
    float* emb;
    int *deg, *rowptr, *cur, *eidx, *bsum;
    cudaGetSymbolAddress((void**)&Ahi, g_Ahi);
    cudaGetSymbolAddress((void**)&Alo, g_Alo);
    cudaGetSymbolAddress((void**)&Hh,  g_Hh);
    cudaGetSymbolAddress((void**)&emb, g_emb);
    cudaGetSymbolAddress((void**)&deg,    g_deg);
    cudaGetSymbolAddress((void**)&rowptr, g_rowptr);
    cudaGetSymbolAddress((void**)&cur,    g_cur);
    cudaGetSymbolAddress((void**)&eidx,   g_eidx);
    cudaGetSymbolAddress((void**)&bsum,   g_bsum);
    cudaGetSymbolAddress((void**)&Whi,  g_Whi);
    cudaGetSymbolAddress((void**)&Wlo,  g_Wlo);

    __half* Ah16 = (__half*)Ahi;                   // trunk A (fp16 single buffer)
    const __half* Wh16 = (const __half*)Whi;
    const __half* Wl16 = (const __half*)Wlo;

    const int* src = adj;
    const int* dst = adj + E;

    int nScanBlk = (N + 1023) / 1024;
    int tilesN  = (N + TM - 1) / TM;
    int tilesNE = (NE + TM - 1) / TM;
    int gN  = tilesN  < 296 ? tilesN  : 296;
    int gNE = tilesNE < 296 ? tilesNE : 296;
    int aggBlk = (N * 32 + 255) / 256;

    // ---- prep + L1 GEMM early, CSR chain after ----
    prep_weights_kernel<<<(5 * 16384 + 255) / 256, 256>>>(W1, W2, W3, P1, P2, Whi, Wlo);
    xhalf_kernel<<<2048, 256>>>(x, Ah16, N);
    zero_int_kernel<<<(N + 255) / 256, 256>>>(deg, N);
    gemm_f16_kernel<<<gN, 256, H_SMEM_BYTES>>>(Ah16, Wh16, Wl16, Hh, N, tilesN);
    hist_kernel<<<(E + 255) / 256, 256>>>(dst, E, deg);
    scan1_kernel<<<nScanBlk, 1024>>>(deg, rowptr, bsum, N);
    scan2_kernel<<<1, 32>>>(bsum, nScanBlk);
    scan3_kernel<<<nScanBlk, 1024>>>(deg, rowptr, cur, bsum, N);
    fill_csr_kernel<<<(E + 255) / 256, 256>>>(src, dst, E, cur, eidx);

    // ---- trunk ----
    agg_kernel<<<aggBlk, 256>>>(Hh, rowptr, eidx, b1, Ah16, nullptr, 1, 0, N);
    gemm_f16_kernel<<<gN, 256, H_SMEM_BYTES>>>(Ah16, Wh16 + 16384, Wl16 + 16384, Hh, N, tilesN);
    agg_kernel<<<aggBlk, 256>>>(Hh, rowptr, eidx, b2, Ah16, nullptr, 1, 0, N);
    gemm_f16_kernel<<<gN, 256, H_SMEM_BYTES>>>(Ah16, Wh16 + 2 * 16384, Wl16 + 2 * 16384, Hh, N, tilesN);
    agg_kernel<<<aggBlk, 256>>>(Hh, rowptr, eidx, b3, nullptr, emb, 0, 1, N);

    // ---- link predictor (bf16 3-pass) ----
    gemm_bf16_kernel<<<gNE, 256, B_SMEM_BYTES>>>(nullptr, nullptr, emb, tedg,
        Whi + 3 * 16384, Wlo + 3 * 16384, pb1, Ahi, Alo, nullptr, nullptr, nullptr,
        NE, tilesNE, 1, 1);
    gemm_bf16_kernel<<<gNE, 256, B_SMEM_BYTES>>>(Ahi, Alo, nullptr, nullptr,
        Whi + 4 * 16384, Wlo + 4 * 16384, pb2, nullptr, nullptr, P3, pb3, out,
        NE, tilesNE, 0, 2);
}

// round 14
// speedup vs baseline: 1.2387x; 1.0181x over previous
#include <cuda_runtime.h>
#include <cuda_bf16.h>
#include <cuda_fp16.h>
#include <math.h>
#include <stdint.h>

// ---------------- problem constants ----------------
#define MAXN 50000
#define MAXE 800000
#define MAXNE 100000
#define D 128

// ---------------- device scratch ----------------
__device__ __nv_bfloat16 g_Ahi[(size_t)(MAXNE + 128) * D];
__device__ __nv_bfloat16 g_Alo[(size_t)(MAXNE + 128) * D];
__device__ __half g_Hh [(size_t)(MAXN + 128) * D];   // fp16 trunk intermediate
__device__ float g_emb[(size_t)MAXN * D];
__device__ int   g_deg[MAXN];
__device__ int   g_rowptr[MAXN + 1];
__device__ int   g_cur[MAXN];
__device__ int   g_eidx[MAXE];
__device__ int   g_bsum[256];
// weights: slots 0..2 = W1..W3 fp16 hi/lo; slots 3..4 = P1,P2 bf16 hi/lo
__device__ __nv_bfloat16 g_Whi[5 * 16384];
__device__ __nv_bfloat16 g_Wlo[5 * 16384];

// ---------------- PTX helpers ----------------
__device__ __forceinline__ uint32_t smem_u32(const void* p) {
    uint32_t a;
    asm("{ .reg .u64 t; cvta.to.shared.u64 t, %1; cvt.u32.u64 %0, t; }" : "=r"(a) : "l"(p));
    return a;
}
__device__ __forceinline__ void ldsm4(uint32_t* r, uint32_t addr) {
    asm volatile("ldmatrix.sync.aligned.m8n8.x4.shared.b16 {%0,%1,%2,%3}, [%4];"
        : "=r"(r[0]), "=r"(r[1]), "=r"(r[2]), "=r"(r[3]) : "r"(addr));
}
__device__ __forceinline__ void mma_bf16(float* c, const uint32_t* a, const uint32_t* b) {
    asm volatile(
        "mma.sync.aligned.m16n8k16.row.col.f32.bf16.bf16.f32 "
        "{%0,%1,%2,%3}, {%4,%5,%6,%7}, {%8,%9}, {%0,%1,%2,%3};"
        : "+f"(c[0]), "+f"(c[1]), "+f"(c[2]), "+f"(c[3])
        : "r"(a[0]), "r"(a[1]), "r"(a[2]), "r"(a[3]), "r"(b[0]), "r"(b[1]));
}
__device__ __forceinline__ void mma_f16(float* c, const uint32_t* a, const uint32_t* b) {
    asm volatile(
        "mma.sync.aligned.m16n8k16.row.col.f32.f16.f16.f32 "
        "{%0,%1,%2,%3}, {%4,%5,%6,%7}, {%8,%9}, {%0,%1,%2,%3};"
        : "+f"(c[0]), "+f"(c[1]), "+f"(c[2]), "+f"(c[3])
        : "r"(a[0]), "r"(a[1]), "r"(a[2]), "r"(a[3]), "r"(b[0]), "r"(b[1]));
}
__device__ __forceinline__ void cp_async16(uint32_t saddr, const void* gptr) {
    asm volatile("cp.async.cg.shared.global [%0], [%1], 16;" :: "r"(saddr), "l"(gptr));
}
#define CP_COMMIT() asm volatile("cp.async.commit_group;" ::: "memory")
template <int NN> __device__ __forceinline__ void cp_wait() {
    asm volatile("cp.async.wait_group %0;" :: "n"(NN) : "memory");
}
__device__ __forceinline__ void split2b(float a, float b, uint32_t& hi, uint32_t& lo) {
    __nv_bfloat162 h = __floats2bfloat162_rn(a, b);
    float ra = a - __bfloat162float(h.x);
    float rb = b - __bfloat162float(h.y);
    __nv_bfloat162 l = __floats2bfloat162_rn(ra, rb);
    hi = *(uint32_t*)&h;
    lo = *(uint32_t*)&l;
}

// ---------------- CSR build kernels ----------------
__global__ void zero_int_kernel(int* p, int n) {
    for (int i = blockIdx.x * blockDim.x + threadIdx.x; i < n; i += gridDim.x * blockDim.x)
        p[i] = 0;
}
__global__ void hist_kernel(const int* __restrict__ dst, int E, int* __restrict__ deg) {
    for (int e = blockIdx.x * blockDim.x + threadIdx.x; e < E; e += gridDim.x * blockDim.x)
        atomicAdd(&deg[dst[e]], 1);
}
__global__ void scan1_kernel(const int* __restrict__ deg, int* __restrict__ rowptr,
                             int* __restrict__ bsum, int n) {
    __shared__ int wsum[32];
    int tid = threadIdx.x, lane = tid & 31, w = tid >> 5;
    int i = blockIdx.x * 1024 + tid;
    int v = (i < n) ? deg[i] : 0;
    int s = v;
    #pragma unroll
    for (int off = 1; off < 32; off <<= 1) {
        int t = __shfl_up_sync(0xFFFFFFFFu, s, off);
        if (lane >= off) s += t;
    }
    if (lane == 31) wsum[w] = s;
    __syncthreads();
    if (w == 0) {
        int ws = wsum[lane];
        #pragma unroll
        for (int off = 1; off < 32; off <<= 1) {
            int t = __shfl_up_sync(0xFFFFFFFFu, ws, off);
            if (lane >= off) ws += t;
        }
        wsum[lane] = ws;
    }
    __syncthreads();
    int prev = (w > 0) ? wsum[w - 1] : 0;
    int incl = prev + s;
    if (i < n) rowptr[i] = incl - v;
    if (tid == 1023) bsum[blockIdx.x] = incl;
}
__global__ void scan2_kernel(int* bsum, int nb) {
    int lane = threadIdx.x;
    int carry = 0;
    for (int base = 0; base < nb; base += 32) {
        int i = base + lane;
        int v = (i < nb) ? bsum[i] : 0;
        int s = v;
        #pragma unroll
        for (int off = 1; off < 32; off <<= 1) {
            int t = __shfl_up_sync(0xFFFFFFFFu, s, off);
            if (lane >= off) s += t;
        }
        if (i < nb) bsum[i] = carry + s - v;
        carry += __shfl_sync(0xFFFFFFFFu, s, 31);
    }
}
__global__ void scan3_kernel(const int* __restrict__ deg, int* __restrict__ rowptr,
                             int* __restrict__ cur, const int* __restrict__ bsum, int n) {
    int i = blockIdx.x * 1024 + threadIdx.x;
    if (i >= n) return;
    int val = rowptr[i] + bsum[blockIdx.x];
    rowptr[i] = val;
    cur[i] = val;
    if (i == n - 1) rowptr[n] = val + deg[n - 1];
}
__global__ void fill_csr_kernel(const int* __restrict__ src, const int* __restrict__ dst,
                                int E, int* __restrict__ cur, int* __restrict__ eidx) {
    for (int e = blockIdx.x * blockDim.x + threadIdx.x; e < E; e += gridDim.x * blockDim.x) {
        int d = dst[e];
        int p = atomicAdd(&cur[d], 1);
        eidx[p] = src[e];
    }
}

// ---------------- prep kernels ----------------
__global__ void prep_weights_kernel(const float* W1, const float* W2, const float* W3,
                                    const float* P1, const float* P2,
                                    __nv_bfloat16* hi, __nv_bfloat16* lo) {
    int idx = blockIdx.x * blockDim.x + threadIdx.x;
    if (idx >= 5 * 16384) return;
    int w = idx >> 14;
    int t = idx & 16383;
    int n = t >> 7;
    int k = t & 127;
    const float* Ws = (w == 0) ? W1 : (w == 1) ? W2 : (w == 2) ? W3 : (w == 3) ? P1 : P2;
    float v = Ws[(k << 7) | n];
    if (w < 3) {
        __half h = __float2half_rn(v);
        float rem = v - __half2float(h);
        ((__half*)hi)[idx] = h;
        ((__half*)lo)[idx] = __float2half_rn(rem);
    } else {
        __nv_bfloat16 h = __float2bfloat16(v);
        float rem = v - __bfloat162float(h);
        hi[idx] = h;
        lo[idx] = __float2bfloat16(rem);
    }
}
__global__ void xhalf_kernel(const float* __restrict__ x, __half* __restrict__ Ah, int N) {
    int n4 = N * 32;
    for (int idx = blockIdx.x * blockDim.x + threadIdx.x; idx < n4; idx += gridDim.x * blockDim.x) {
        float4 v = ((const float4*)x)[idx];
        __half2 h01 = __floats2half2_rn(v.x, v.y);
        __half2 h23 = __floats2half2_rn(v.z, v.w);
        uint2 p;
        p.x = *(uint32_t*)&h01; p.y = *(uint32_t*)&h23;
        *(uint2*)(Ah + (size_t)idx * 4) = p;
    }
}

// ================= fp16 2-pass GEMM (trunk), A double-buffered =================
#define ASTRIDE 136
#define TM 64
#define ABUF (TM * ASTRIDE)
#define WBUF (128 * ASTRIDE)
#define H_SA0 0
#define H_SA1 ABUF
#define H_SWH (2 * ABUF)
#define H_SWL (2 * ABUF + WBUF)
#define H_ELEMS (2 * ABUF + 2 * WBUF)          // 52224 fp16 = 104448 B/CTA
#define H_SMEM_BYTES (H_ELEMS * 2 + 64)

__global__ void __launch_bounds__(256, 2)
gemm_f16_kernel(const __half* __restrict__ A,
                const __half* __restrict__ Wt_hi, const __half* __restrict__ Wt_lo,
                __half* __restrict__ Ch, int M, int numTiles) {
    extern __shared__ __half smh[];
    uint32_t sbase = smem_u32(smh);
    int tid = threadIdx.x, wid = tid >> 5, lane = tid & 31;

    {
        const uint4* wh = (const uint4*)Wt_hi;
        const uint4* wl = (const uint4*)Wt_lo;
        for (int i = tid; i < 2048; i += 256) {
            int r = i >> 4, c = i & 15;
            *(uint4*)(smh + H_SWH + r * ASTRIDE + c * 8) = wh[i];
            *(uint4*)(smh + H_SWL + r * ASTRIDE + c * 8) = wl[i];
        }
    }

    int mwid = wid >> 2;
    int nwid = wid & 3;
    int mrow0 = mwid << 5;
    int ncol0 = nwid << 5;

    uint32_t aRel = (uint32_t)(mrow0 + (lane & 15)) * (ASTRIDE * 2)
                  + (uint32_t)(((lane >> 4) << 3) * 2);
    uint32_t bN = (uint32_t)(ncol0 + ((lane >> 4) << 3) + (lane & 7));
    uint32_t bKB = (uint32_t)((((lane >> 3) & 1) << 3) * 2);
    uint32_t bHiBase = sbase + (H_SWH * 2) + bN * (ASTRIDE * 2) + bKB;
    uint32_t bLoBase = bHiBase + WBUF * 2;

    auto stage = [&](int tile, int buf) {
        int row0 = tile * TM;
        uint32_t sab = (buf ? H_SA1 : H_SA0) * 2;
        #pragma unroll
        for (int it = 0; it < 4; it++) {
            int idx = it * 256 + tid;
            int r = idx >> 4, c = idx & 15;
            size_t goff = (size_t)(row0 + r) * D + c * 8;
            uint32_t soff = (r * ASTRIDE + c * 8) * 2;
            cp_async16(sbase + sab + soff, A + goff);
        }
        CP_COMMIT();
    };

    int t = blockIdx.x;
    int parity = 0;
    if (t < numTiles) stage(t, 0);
    for (; t < numTiles; t += gridDim.x, parity ^= 1) {
        int nxt = t + gridDim.x;
        if (nxt < numTiles) { stage(nxt, parity ^ 1); cp_wait<1>(); }
        else cp_wait<0>();
        __syncthreads();

        uint32_t a0 = sbase + ((parity ? H_SA1 : H_SA0) * 2) + aRel;
        uint32_t a1 = a0 + 16 * (ASTRIDE * 2);
        int row0 = t * TM;

        float acc[2][4][4];
        #pragma unroll
        for (int mt = 0; mt < 2; mt++)
            #pragma unroll
            for (int nt = 0; nt < 4; nt++)
                #pragma unroll
                for (int q = 0; q < 4; q++) acc[mt][nt][q] = 0.0f;

        #pragma unroll
        for (int ks = 0; ks < 8; ks++) {
            uint32_t koffB = (uint32_t)(ks * 32);
            uint32_t af[2][4];
            ldsm4(af[0], a0 + koffB);
            ldsm4(af[1], a1 + koffB);
            uint32_t bh[4][2], bl[4][2];
            #pragma unroll
            for (int np = 0; np < 2; np++) {
                uint32_t r4[4];
                ldsm4(r4, bHiBase + (uint32_t)(np * 16 * ASTRIDE * 2) + koffB);
                bh[2 * np][0] = r4[0]; bh[2 * np][1] = r4[1];
                bh[2 * np + 1][0] = r4[2]; bh[2 * np + 1][1] = r4[3];
                ldsm4(r4, bLoBase + (uint32_t)(np * 16 * ASTRIDE * 2) + koffB);
                bl[2 * np][0] = r4[0]; bl[2 * np][1] = r4[1];
                bl[2 * np + 1][0] = r4[2]; bl[2 * np + 1][1] = r4[3];
            }
            #pragma unroll
            for (int mt = 0; mt < 2; mt++)
                #pragma unroll
                for (int nt = 0; nt < 4; nt++) {
                    mma_f16(acc[mt][nt], af[mt], bh[nt]);
                    mma_f16(acc[mt][nt], af[mt], bl[nt]);
                }
        }

        int cbase = ncol0 + ((lane & 3) << 1);
        int rbase = row0 + mrow0 + (lane >> 2);
        #pragma unroll
        for (int mt = 0; mt < 2; mt++) {
            #pragma unroll
            for (int half = 0; half < 2; half++) {
                int gr = rbase + mt * 16 + half * 8;
                if (gr >= M) continue;
                __half* cp = Ch + (size_t)gr * D;
                #pragma unroll
                for (int nt = 0; nt < 4; nt++) {
                    int col = cbase + nt * 8;
                    __half2 hp = __floats2half2_rn(acc[mt][nt][2 * half],
                                                   acc[mt][nt][2 * half + 1]);
                    *(uint32_t*)(cp + col) = *(uint32_t*)&hp;
                }
            }
        }
        __syncthreads();
    }
}

// ================= bf16 3-pass GEMM (link predictor) =================
#define B_SAHI 0
#define B_SALO ABUF
#define B_SWH (2 * ABUF)
#define B_SWL (2 * ABUF + WBUF)
#define B_ELEMS (2 * ABUF + 2 * WBUF)
#define B_SMEM_BYTES (B_ELEMS * 2 + (512 + 256 + 8) * 4)

__global__ void __launch_bounds__(256, 2)
gemm_bf16_kernel(const __nv_bfloat16* __restrict__ Ahi, const __nv_bfloat16* __restrict__ Alo,
                 const float* __restrict__ embf, const int* __restrict__ tedg,
                 const __nv_bfloat16* __restrict__ Wt_hi, const __nv_bfloat16* __restrict__ Wt_lo,
                 const float* __restrict__ bias,
                 __nv_bfloat16* __restrict__ OutHi, __nv_bfloat16* __restrict__ OutLo,
                 const float* __restrict__ P3, const float* __restrict__ pb3,
                 float* __restrict__ outF,
                 int M, int numTiles, int stagemode, int epimode) {
    extern __shared__ __nv_bfloat16 sm[];
    uint32_t sbase = smem_u32(sm);
    float* fpart = (float*)(sm + B_ELEMS);
    float* fP3 = fpart + 512;
    float* fpb3 = fP3 + 256;
    int tid = threadIdx.x, wid = tid >> 5, lane = tid & 31;

    {
        const uint4* wh = (const uint4*)Wt_hi;
        const uint4* wl = (const uint4*)Wt_lo;
        for (int i = tid; i < 2048; i += 256) {
            int r = i >> 4, c = i & 15;
            *(uint4*)(sm + B_SWH + r * ASTRIDE + c * 8) = wh[i];
            *(uint4*)(sm + B_SWL + r * ASTRIDE + c * 8) = wl[i];
        }
        if (epimode == 2) {
            fP3[tid] = P3[tid];
            if (tid < 2) fpb3[tid] = pb3[tid];
        }
    }

    int mwid = wid >> 2;
    int nwid = wid & 3;
    int mrow0 = mwid << 5;
    int ncol0 = nwid << 5;

    uint32_t aRel = (uint32_t)(mrow0 + (lane & 15)) * (ASTRIDE * 2)
                  + (uint32_t)(((lane >> 4) << 3) * 2);
    uint32_t aHi0 = sbase + (B_SAHI * 2) + aRel;
    uint32_t aHi1 = aHi0 + 16 * (ASTRIDE * 2);
    uint32_t aLo0 = aHi0 + ABUF * 2;
    uint32_t aLo1 = aHi1 + ABUF * 2;

    uint32_t bN = (uint32_t)(ncol0 + ((lane >> 4) << 3) + (lane & 7));
    uint32_t bKB = (uint32_t)((((lane >> 3) & 1) << 3) * 2);
    uint32_t bHiBase = sbase + (B_SWH * 2) + bN * (ASTRIDE * 2) + bKB;
    uint32_t bLoBase = bHiBase + WBUF * 2;

    for (int t = blockIdx.x; t < numTiles; t += gridDim.x) {
        int row0 = t * TM;

        if (stagemode == 0) {
            #pragma unroll
            for (int it = 0; it < 4; it++) {
                int idx = it * 256 + tid;
                int r = idx >> 4, c = idx & 15;
                size_t goff = (size_t)(row0 + r) * D + c * 8;
                uint32_t soff = (r * ASTRIDE + c * 8) * 2;
                cp_async16(sbase + (B_SAHI * 2) + soff, Ahi + goff);
                cp_async16(sbase + (B_SALO * 2) + soff, Alo + goff);
            }
            CP_COMMIT();
            cp_wait<0>();
        } else {
            #pragma unroll
            for (int it = 0; it < 8; it++) {
                int idx = it * 256 + tid;
                int r = idx >> 5;
                int c4 = idx & 31;
                int grow = row0 + r;
                float4 v;
                if (grow < M) {
                    int s = tedg[2 * grow];
                    int d = tedg[2 * grow + 1];
                    float4 a = *(const float4*)(embf + (size_t)s * D + c4 * 4);
                    float4 b = *(const float4*)(embf + (size_t)d * D + c4 * 4);
                    v = make_float4(a.x * b.x, a.y * b.y, a.z * b.z, a.w * b.w);
                } else {
                    v = make_float4(0.f, 0.f, 0.f, 0.f);
                }
                uint2 hp, lp;
                split2b(v.x, v.y, hp.x, lp.x);
                split2b(v.z, v.w, hp.y, lp.y);
                *(uint2*)(sm + B_SAHI + r * ASTRIDE + c4 * 4) = hp;
                *(uint2*)(sm + B_SALO + r * ASTRIDE + c4 * 4) = lp;
            }
        }
        __syncthreads();

        float acc[2][4][4];
        #pragma unroll
        for (int mt = 0; mt < 2; mt++)
            #pragma unroll
            for (int nt = 0; nt < 4; nt++)
                #pragma unroll
                for (int q = 0; q < 4; q++) acc[mt][nt][q] = 0.0f;

        #pragma unroll
        for (int ks = 0; ks < 8; ks++) {
            uint32_t koffB = (uint32_t)(ks * 32);
            uint32_t ah[2][4], al[2][4];
            ldsm4(ah[0], aHi0 + koffB);
            ldsm4(ah[1], aHi1 + koffB);
            ldsm4(al[0], aLo0 + koffB);
            ldsm4(al[1], aLo1 + koffB);
            uint32_t bh[4][2], bl[4][2];
            #pragma unroll
            for (int np = 0; np < 2; np++) {
                uint32_t r4[4];
                ldsm4(r4, bHiBase + (uint32_t)(np * 16 * ASTRIDE * 2) + koffB);
                bh[2 * np][0] = r4[0]; bh[2 * np][1] = r4[1];
                bh[2 * np + 1][0] = r4[2]; bh[2 * np + 1][1] = r4[3];
                ldsm4(r4, bLoBase + (uint32_t)(np * 16 * ASTRIDE * 2) + koffB);
                bl[2 * np][0] = r4[0]; bl[2 * np][1] = r4[1];
                bl[2 * np + 1][0] = r4[2]; bl[2 * np + 1][1] = r4[3];
            }
            #pragma unroll
            for (int mt = 0; mt < 2; mt++)
                #pragma unroll
                for (int nt = 0; nt < 4; nt++) {
                    mma_bf16(acc[mt][nt], ah[mt], bh[nt]);
                    mma_bf16(acc[mt][nt], ah[mt], bl[nt]);
                    mma_bf16(acc[mt][nt], al[mt], bh[nt]);
                }
        }

        int cbase = ncol0 + ((lane & 3) << 1);

        if (epimode == 2) {
            float q0a[4], q1a[4];
            #pragma unroll
            for (int mt = 0; mt < 2; mt++) {
                #pragma unroll
                for (int half = 0; half < 2; half++) {
                    float q0 = 0.f, q1 = 0.f;
                    #pragma unroll
                    for (int nt = 0; nt < 4; nt++) {
                        int col = cbase + nt * 8;
                        float z0 = fmaxf(acc[mt][nt][2 * half] + bias[col], 0.f);
                        float z1 = fmaxf(acc[mt][nt][2 * half + 1] + bias[col + 1], 0.f);
                        q0 += z0 * fP3[2 * col] + z1 * fP3[2 * (col + 1)];
                        q1 += z0 * fP3[2 * col + 1] + z1 * fP3[2 * (col + 1) + 1];
                    }
                    q0 += __shfl_xor_sync(0xFFFFFFFFu, q0, 1);
                    q0 += __shfl_xor_sync(0xFFFFFFFFu, q0, 2);
                    q1 += __shfl_xor_sync(0xFFFFFFFFu, q1, 1);
                    q1 += __shfl_xor_sync(0xFFFFFFFFu, q1, 2);
                    q0a[mt * 2 + half] = q0;
                    q1a[mt * 2 + half] = q1;
                    if (nwid != 0 && (lane & 3) == 0) {
                        int rl = mrow0 + mt * 16 + half * 8 + (lane >> 2);
                        fpart[rl * 8 + nwid * 2]     = q0;
                        fpart[rl * 8 + nwid * 2 + 1] = q1;
                    }
                }
            }
            __syncthreads();
            if (nwid == 0 && (lane & 3) == 0) {
                #pragma unroll
                for (int mt = 0; mt < 2; mt++) {
                    #pragma unroll
                    for (int half = 0; half < 2; half++) {
                        int rl = mrow0 + mt * 16 + half * 8 + (lane >> 2);
                        int gr = row0 + rl;
                        if (gr < M) {
                            float z0 = q0a[mt * 2 + half] + fpb3[0];
                            float z1 = q1a[mt * 2 + half] + fpb3[1];
                            #pragma unroll
                            for (int nw = 1; nw < 4; nw++) {
                                z0 += fpart[rl * 8 + nw * 2];
                                z1 += fpart[rl * 8 + nw * 2 + 1];
                            }
                            float nrm = fmaxf(sqrtf(z0 * z0 + z1 * z1), 1e-12f);
                            z0 /= nrm; z1 /= nrm;
                            float mm = fmaxf(z0, z1);
                            float lse = mm + logf(expf(z0 - mm) + expf(z1 - mm));
                            outF[2 * gr]     = z0 - lse;
                            outF[2 * gr + 1] = z1 - lse;
                        }
                    }
                }
            }
        } else {
            int rbase = row0 + mrow0 + (lane >> 2);
            #pragma unroll
            for (int mt = 0; mt < 2; mt++) {
                #pragma unroll
                for (int half = 0; half < 2; half++) {
                    int gr = rbase + mt * 16 + half * 8;
                    if (gr >= M) continue;
                    #pragma unroll
                    for (int nt = 0; nt < 4; nt++) {
                        int col = cbase + nt * 8;
                        float o0 = fmaxf(acc[mt][nt][2 * half] + bias[col], 0.f);
                        float o1 = fmaxf(acc[mt][nt][2 * half + 1] + bias[col + 1], 0.f);
                        uint32_t hp, lp;
                        split2b(o0, o1, hp, lp);
                        *(uint32_t*)(OutHi + (size_t)gr * D + col) = hp;
                        *(uint32_t*)(OutLo + (size_t)gr * D + col) = lp;
                    }
                }
            }
        }
        __syncthreads();
    }
}

// ---------------- aggregation: warp-per-dst, uniform index loads, unroll-8 ----------------
__global__ void agg_kernel(const __half* __restrict__ H, const int* __restrict__ rowptr,
                           const int* __restrict__ eidx, const float* __restrict__ bias,
                           __half* __restrict__ OutH, float* __restrict__ OutF,
                           int relu, int outmode, int N) {
    int gw = (blockIdx.x * blockDim.x + threadIdx.x) >> 5;
    int lane = threadIdx.x & 31;
    if (gw >= N) return;
    int beg = rowptr[gw], end = rowptr[gw + 1];
    float4 acc = make_float4(0.f, 0.f, 0.f, 0.f);
    int coff = lane << 2;
    int j = beg;
    #pragma unroll 1
    for (; j + 8 <= end; j += 8) {
        int s0 = eidx[j],     s1 = eidx[j + 1], s2 = eidx[j + 2], s3 = eidx[j + 3];
        int s4 = eidx[j + 4], s5 = eidx[j + 5], s6 = eidx[j + 6], s7 = eidx[j + 7];
        uint2 r0 = *(const uint2*)(H + (size_t)s0 * D + coff);
        uint2 r1 = *(const uint2*)(H + (size_t)s1 * D + coff);
        uint2 r2 = *(const uint2*)(H + (size_t)s2 * D + coff);
        uint2 r3 = *(const uint2*)(H + (size_t)s3 * D + coff);
        uint2 r4 = *(const uint2*)(H + (size_t)s4 * D + coff);
        uint2 r5 = *(const uint2*)(H + (size_t)s5 * D + coff);
        uint2 r6 = *(const uint2*)(H + (size_t)s6 * D + coff);
        uint2 r7 = *(const uint2*)(H + (size_t)s7 * D + coff);
        float2 a0 = __half22float2(*(__half2*)&r0.x), b0 = __half22float2(*(__half2*)&r0.y);
        float2 a1 = __half22float2(*(__half2*)&r1.x), b1 = __half22float2(*(__half2*)&r1.y);
        float2 a2 = __half22float2(*(__half2*)&r2.x), b2 = __half22float2(*(__half2*)&r2.y);
        float2 a3 = __half22float2(*(__half2*)&r3.x), b3 = __half22float2(*(__half2*)&r3.y);
        float2 a4 = __half22float2(*(__half2*)&r4.x), b4 = __half22float2(*(__half2*)&r4.y);
        float2 a5 = __half22float2(*(__half2*)&r5.x), b5 = __half22float2(*(__half2*)&r5.y);
        float2 a6 = __half22float2(*(__half2*)&r6.x), b6 = __half22float2(*(__half2*)&r6.y);
        float2 a7 = __half22float2(*(__half2*)&r7.x), b7 = __half22float2(*(__half2*)&r7.y);
        acc.x += a0.x; acc.y += a0.y; acc.z += b0.x; acc.w += b0.y;
        acc.x += a1.x; acc.y += a1.y; acc.z += b1.x; acc.w += b1.y;
        acc.x += a2.x; acc.y += a2.y; acc.z += b2.x; acc.w += b2.y;
        acc.x += a3.x; acc.y += a3.y; acc.z += b3.x; acc.w += b3.y;
        acc.x += a4.x; acc.y += a4.y; acc.z += b4.x; acc.w += b4.y;
        acc.x += a5.x; acc.y += a5.y; acc.z += b5.x; acc.w += b5.y;
        acc.x += a6.x; acc.y += a6.y; acc.z += b6.x; acc.w += b6.y;
        acc.x += a7.x; acc.y += a7.y; acc.z += b7.x; acc.w += b7.y;
    }
    for (; j < end; j++) {
        int s = eidx[j];
        uint2 raw = *(const uint2*)(H + (size_t)s * D + coff);
        float2 f01 = __half22float2(*(__half2*)&raw.x);
        float2 f23 = __half22float2(*(__half2*)&raw.y);
        acc.x += f01.x; acc.y += f01.y; acc.z += f23.x; acc.w += f23.y;
    }
    float4 bv = *(const float4*)(bias + coff);
    acc.x += bv.x; acc.y += bv.y; acc.z += bv.z; acc.w += bv.w;
    if (relu) {
        acc.x = fmaxf(acc.x, 0.f); acc.y = fmaxf(acc.y, 0.f);
        acc.z = fmaxf(acc.z, 0.f); acc.w = fmaxf(acc.w, 0.f);
    }
    if (outmode == 0) {
        __half2 h01 = __floats2half2_rn(acc.x, acc.y);
        __half2 h23 = __floats2half2_rn(acc.z, acc.w);
        uint2 p;
        p.x = *(uint32_t*)&h01; p.y = *(uint32_t*)&h23;
        *(uint2*)(OutH + (size_t)gw * D + coff) = p;
    } else {
        *(float4*)(OutF + (size_t)gw * D + coff) = acc;
    }
}

// ---------------- launch ----------------
extern "C" void kernel_launch(void* const* d_in, const int* in_sizes, int n_in,
                              void* d_out, int out_size) {
    const float* x    = (const float*)d_in[0];
    const int*   adj  = (const int*)d_in[1];
    const int*   tedg = (const int*)d_in[2];
    const float* W1 = (const float*)d_in[3];  const float* b1  = (const float*)d_in[4];
    const float* W2 = (const float*)d_in[5];  const float* b2  = (const float*)d_in[6];
    const float* W3 = (const float*)d_in[7];  const float* b3  = (const float*)d_in[8];
    const float* P1 = (const float*)d_in[9];  const float* pb1 = (const float*)d_in[10];
    const float* P2 = (const float*)d_in[11]; const float* pb2 = (const float*)d_in[12];
    const float* P3 = (const float*)d_in[13]; const float* pb3 = (const float*)d_in[14];
    float* out = (float*)d_out;

    int N  = in_sizes[0] / D;
    int E  = in_sizes[1] / 2;
    int NE = in_sizes[2] / 2;

    cudaFuncSetAttribute((const void*)gemm_f16_kernel,
                         cudaFuncAttributeMaxDynamicSharedMemorySize, H_SMEM_BYTES);
    cudaFuncSetAttribute((const void*)gemm_bf16_kernel,
                         cudaFuncAttributeMaxDynamicSharedMemorySize, B_SMEM_BYTES);

    __nv_bfloat16 *Ahi, *Alo, *Whi, *Wlo;
    __half* Hh;
    float* emb;
    int *deg, *rowptr, *cur, *eidx, *bsum;
    cudaGetSymbolAddress((void**)&Ahi, g_Ahi);
    cudaGetSymbolAddress((void**)&Alo, g_Alo);
    cudaGetSymbolAddress((void**)&Hh,  g_Hh);
    cudaGetSymbolAddress((void**)&emb, g_emb);
    cudaGetSymbolAddress((void**)&deg,    g_deg);
    cudaGetSymbolAddress((void**)&rowptr, g_rowptr);
    cudaGetSymbolAddress((void**)&cur,    g_cur);
    cudaGetSymbolAddress((void**)&eidx,   g_eidx);
    cudaGetSymbolAddress((void**)&bsum,   g_bsum);
    cudaGetSymbolAddress((void**)&Whi,  g_Whi);
    cudaGetSymbolAddress((void**)&Wlo,  g_Wlo);

    __half* Ah16 = (__half*)Ahi;                   // trunk A (fp16 single buffer)
    const __half* Wh16 = (const __half*)Whi;
    const __half* Wl16 = (const __half*)Wlo;

    const int* src = adj;
    const int* dst = adj + E;

    int nScanBlk = (N + 1023) / 1024;
    int tilesN  = (N + TM - 1) / TM;
    int tilesNE = (NE + TM - 1) / TM;
    int gN  = tilesN  < 296 ? tilesN  : 296;
    int gNE = tilesNE < 296 ? tilesNE : 296;
    int aggBlk = (N * 32 + 255) / 256;

    // ---- prep + L1 GEMM early, CSR chain after ----
    prep_weights_kernel<<<(5 * 16384 + 255) / 256, 256>>>(W1, W2, W3, P1, P2, Whi, Wlo);
    xhalf_kernel<<<2048, 256>>>(x, Ah16, N);
    zero_int_kernel<<<(N + 255) / 256, 256>>>(deg, N);
    gemm_f16_kernel<<<gN, 256, H_SMEM_BYTES>>>(Ah16, Wh16, Wl16, Hh, N, tilesN);
    hist_kernel<<<(E + 255) / 256, 256>>>(dst, E, deg);
    scan1_kernel<<<nScanBlk, 1024>>>(deg, rowptr, bsum, N);
    scan2_kernel<<<1, 32>>>(bsum, nScanBlk);
    scan3_kernel<<<nScanBlk, 1024>>>(deg, rowptr, cur, bsum, N);
    fill_csr_kernel<<<(E + 255) / 256, 256>>>(src, dst, E, cur, eidx);

    // ---- trunk ----
    agg_kernel<<<aggBlk, 256>>>(Hh, rowptr, eidx, b1, Ah16, nullptr, 1, 0, N);
    gemm_f16_kernel<<<gN, 256, H_SMEM_BYTES>>>(Ah16, Wh16 + 16384, Wl16 + 16384, Hh, N, tilesN);
    agg_kernel<<<aggBlk, 256>>>(Hh, rowptr, eidx, b2, Ah16, nullptr, 1, 0, N);
    gemm_f16_kernel<<<gN, 256, H_SMEM_BYTES>>>(Ah16, Wh16 + 2 * 16384, Wl16 + 2 * 16384, Hh, N, tilesN);
    agg_kernel<<<aggBlk, 256>>>(Hh, rowptr, eidx, b3, nullptr, emb, 0, 1, N);

    // ---- link predictor (bf16 3-pass) ----
    gemm_bf16_kernel<<<gNE, 256, B_SMEM_BYTES>>>(nullptr, nullptr, emb, tedg,
        Whi + 3 * 16384, Wlo + 3 * 16384, pb1, Ahi, Alo, nullptr, nullptr, nullptr,
        NE, tilesNE, 1, 1);
    gemm_bf16_kernel<<<gNE, 256, B_SMEM_BYTES>>>(Ahi, Alo, nullptr, nullptr,
        Whi + 4 * 16384, Wlo + 4 * 16384, pb2, nullptr, nullptr, P3, pb3, out,
        NE, tilesNE, 0, 2);
}

// round 15
// speedup vs baseline: 1.2634x; 1.0200x over previous
#include <cuda_runtime.h>
#include <cuda_bf16.h>
#include <cuda_fp16.h>
#include <math.h>
#include <stdint.h>

// ---------------- problem constants ----------------
#define MAXN 50000
#define MAXE 800000
#define MAXNE 100000
#define D 128

// ---------------- device scratch ----------------
__device__ __nv_bfloat16 g_Ahi[(size_t)(MAXNE + 128) * D];
__device__ __nv_bfloat16 g_Alo[(size_t)(MAXNE + 128) * D];
__device__ __half g_Hh [(size_t)(MAXN + 128) * D];   // fp16 trunk intermediate
__device__ float g_emb[(size_t)MAXN * D];
__device__ int   g_deg[MAXN];
__device__ int   g_rowptr[MAXN + 1];
__device__ int   g_cur[MAXN];
__device__ int   g_eidx[MAXE];
__device__ int   g_bsum[256];
// weights: slots 0..2 = W1..W3 fp16 hi/lo; slots 3..4 = P1,P2 bf16 hi/lo
__device__ __nv_bfloat16 g_Whi[5 * 16384];
__device__ __nv_bfloat16 g_Wlo[5 * 16384];

// ---------------- PTX helpers ----------------
__device__ __forceinline__ uint32_t smem_u32(const void* p) {
    uint32_t a;
    asm("{ .reg .u64 t; cvta.to.shared.u64 t, %1; cvt.u32.u64 %0, t; }" : "=r"(a) : "l"(p));
    return a;
}
__device__ __forceinline__ void ldsm4(uint32_t* r, uint32_t addr) {
    asm volatile("ldmatrix.sync.aligned.m8n8.x4.shared.b16 {%0,%1,%2,%3}, [%4];"
        : "=r"(r[0]), "=r"(r[1]), "=r"(r[2]), "=r"(r[3]) : "r"(addr));
}
__device__ __forceinline__ void mma_bf16(float* c, const uint32_t* a, const uint32_t* b) {
    asm volatile(
        "mma.sync.aligned.m16n8k16.row.col.f32.bf16.bf16.f32 "
        "{%0,%1,%2,%3}, {%4,%5,%6,%7}, {%8,%9}, {%0,%1,%2,%3};"
        : "+f"(c[0]), "+f"(c[1]), "+f"(c[2]), "+f"(c[3])
        : "r"(a[0]), "r"(a[1]), "r"(a[2]), "r"(a[3]), "r"(b[0]), "r"(b[1]));
}
__device__ __forceinline__ void mma_f16(float* c, const uint32_t* a, const uint32_t* b) {
    asm volatile(
        "mma.sync.aligned.m16n8k16.row.col.f32.f16.f16.f32 "
        "{%0,%1,%2,%3}, {%4,%5,%6,%7}, {%8,%9}, {%0,%1,%2,%3};"
        : "+f"(c[0]), "+f"(c[1]), "+f"(c[2]), "+f"(c[3])
        : "r"(a[0]), "r"(a[1]), "r"(a[2]), "r"(a[3]), "r"(b[0]), "r"(b[1]));
}
__device__ __forceinline__ void cp_async16(uint32_t saddr, const void* gptr) {
    asm volatile("cp.async.cg.shared.global [%0], [%1], 16;" :: "r"(saddr), "l"(gptr));
}
#define CP_COMMIT() asm volatile("cp.async.commit_group;" ::: "memory")
template <int NN> __device__ __forceinline__ void cp_wait() {
    asm volatile("cp.async.wait_group %0;" :: "n"(NN) : "memory");
}
__device__ __forceinline__ void split2b(float a, float b, uint32_t& hi, uint32_t& lo) {
    __nv_bfloat162 h = __floats2bfloat162_rn(a, b);
    float ra = a - __bfloat162float(h.x);
    float rb = b - __bfloat162float(h.y);
    __nv_bfloat162 l = __floats2bfloat162_rn(ra, rb);
    hi = *(uint32_t*)&h;
    lo = *(uint32_t*)&l;
}

// ---------------- fused setup: weight prep + x->fp16 + deg zero ----------------
__global__ void setup_kernel(const float* __restrict__ W1, const float* __restrict__ W2,
                             const float* __restrict__ W3, const float* __restrict__ P1,
                             const float* __restrict__ P2,
                             __nv_bfloat16* __restrict__ hi, __nv_bfloat16* __restrict__ lo,
                             const float* __restrict__ x, __half* __restrict__ Ah,
                             int* __restrict__ deg, int N) {
    int stride = gridDim.x * blockDim.x;
    int gid = blockIdx.x * blockDim.x + threadIdx.x;
    // 1) weights: W1..W3 -> fp16 hi/lo, P1,P2 -> bf16 hi/lo (transposed [n][k])
    for (int idx = gid; idx < 5 * 16384; idx += stride) {
        int w = idx >> 14;
        int t = idx & 16383;
        int n = t >> 7;
        int k = t & 127;
        const float* Ws = (w == 0) ? W1 : (w == 1) ? W2 : (w == 2) ? W3 : (w == 3) ? P1 : P2;
        float v = Ws[(k << 7) | n];
        if (w < 3) {
            __half h = __float2half_rn(v);
            float rem = v - __half2float(h);
            ((__half*)hi)[idx] = h;
            ((__half*)lo)[idx] = __float2half_rn(rem);
        } else {
            __nv_bfloat16 h = __float2bfloat16(v);
            float rem = v - __bfloat162float(h);
            hi[idx] = h;
            lo[idx] = __float2bfloat16(rem);
        }
    }
    // 2) x fp32 -> fp16
    int n4 = N * 32;
    for (int idx = gid; idx < n4; idx += stride) {
        float4 v = ((const float4*)x)[idx];
        __half2 h01 = __floats2half2_rn(v.x, v.y);
        __half2 h23 = __floats2half2_rn(v.z, v.w);
        uint2 p;
        p.x = *(uint32_t*)&h01; p.y = *(uint32_t*)&h23;
        *(uint2*)(Ah + (size_t)idx * 4) = p;
    }
    // 3) zero deg
    for (int i = gid; i < N; i += stride) deg[i] = 0;
}

// ---------------- CSR build kernels ----------------
__global__ void hist_kernel(const int* __restrict__ dst, int E, int* __restrict__ deg) {
    for (int e = blockIdx.x * blockDim.x + threadIdx.x; e < E; e += gridDim.x * blockDim.x)
        atomicAdd(&deg[dst[e]], 1);
}
__global__ void scan1_kernel(const int* __restrict__ deg, int* __restrict__ rowptr,
                             int* __restrict__ bsum, int n) {
    __shared__ int wsum[32];
    int tid = threadIdx.x, lane = tid & 31, w = tid >> 5;
    int i = blockIdx.x * 1024 + tid;
    int v = (i < n) ? deg[i] : 0;
    int s = v;
    #pragma unroll
    for (int off = 1; off < 32; off <<= 1) {
        int t = __shfl_up_sync(0xFFFFFFFFu, s, off);
        if (lane >= off) s += t;
    }
    if (lane == 31) wsum[w] = s;
    __syncthreads();
    if (w == 0) {
        int ws = wsum[lane];
        #pragma unroll
        for (int off = 1; off < 32; off <<= 1) {
            int t = __shfl_up_sync(0xFFFFFFFFu, ws, off);
            if (lane >= off) ws += t;
        }
        wsum[lane] = ws;
    }
    __syncthreads();
    int prev = (w > 0) ? wsum[w - 1] : 0;
    int incl = prev + s;
    if (i < n) rowptr[i] = incl - v;
    if (tid == 1023) bsum[blockIdx.x] = incl;
}
__global__ void scan2_kernel(int* bsum, int nb) {
    int lane = threadIdx.x;
    int carry = 0;
    for (int base = 0; base < nb; base += 32) {
        int i = base + lane;
        int v = (i < nb) ? bsum[i] : 0;
        int s = v;
        #pragma unroll
        for (int off = 1; off < 32; off <<= 1) {
            int t = __shfl_up_sync(0xFFFFFFFFu, s, off);
            if (lane >= off) s += t;
        }
        if (i < nb) bsum[i] = carry + s - v;
        carry += __shfl_sync(0xFFFFFFFFu, s, 31);
    }
}
__global__ void scan3_kernel(const int* __restrict__ deg, int* __restrict__ rowptr,
                             int* __restrict__ cur, const int* __restrict__ bsum, int n) {
    int i = blockIdx.x * 1024 + threadIdx.x;
    if (i >= n) return;
    int val = rowptr[i] + bsum[blockIdx.x];
    rowptr[i] = val;
    cur[i] = val;
    if (i == n - 1) rowptr[n] = val + deg[n - 1];
}
__global__ void fill_csr_kernel(const int* __restrict__ src, const int* __restrict__ dst,
                                int E, int* __restrict__ cur, int* __restrict__ eidx) {
    for (int e = blockIdx.x * blockDim.x + threadIdx.x; e < E; e += gridDim.x * blockDim.x) {
        int d = dst[e];
        int p = atomicAdd(&cur[d], 1);
        eidx[p] = src[e];
    }
}

// ================= fp16 2-pass GEMM (trunk), A double-buffered =================
#define ASTRIDE 136
#define TM 64
#define ABUF (TM * ASTRIDE)
#define WBUF (128 * ASTRIDE)
#define H_SA0 0
#define H_SA1 ABUF
#define H_SWH (2 * ABUF)
#define H_SWL (2 * ABUF + WBUF)
#define H_ELEMS (2 * ABUF + 2 * WBUF)
#define H_SMEM_BYTES (H_ELEMS * 2 + 64)

__global__ void __launch_bounds__(256, 2)
gemm_f16_kernel(const __half* __restrict__ A,
                const __half* __restrict__ Wt_hi, const __half* __restrict__ Wt_lo,
                __half* __restrict__ Ch, int M, int numTiles) {
    extern __shared__ __half smh[];
    uint32_t sbase = smem_u32(smh);
    int tid = threadIdx.x, wid = tid >> 5, lane = tid & 31;

    {
        const uint4* wh = (const uint4*)Wt_hi;
        const uint4* wl = (const uint4*)Wt_lo;
        for (int i = tid; i < 2048; i += 256) {
            int r = i >> 4, c = i & 15;
            *(uint4*)(smh + H_SWH + r * ASTRIDE + c * 8) = wh[i];
            *(uint4*)(smh + H_SWL + r * ASTRIDE + c * 8) = wl[i];
        }
    }

    int mwid = wid >> 2;
    int nwid = wid & 3;
    int mrow0 = mwid << 5;
    int ncol0 = nwid << 5;

    uint32_t aRel = (uint32_t)(mrow0 + (lane & 15)) * (ASTRIDE * 2)
                  + (uint32_t)(((lane >> 4) << 3) * 2);
    uint32_t bN = (uint32_t)(ncol0 + ((lane >> 4) << 3) + (lane & 7));
    uint32_t bKB = (uint32_t)((((lane >> 3) & 1) << 3) * 2);
    uint32_t bHiBase = sbase + (H_SWH * 2) + bN * (ASTRIDE * 2) + bKB;
    uint32_t bLoBase = bHiBase + WBUF * 2;

    auto stage = [&](int tile, int buf) {
        int row0 = tile * TM;
        uint32_t sab = (buf ? H_SA1 : H_SA0) * 2;
        #pragma unroll
        for (int it = 0; it < 4; it++) {
            int idx = it * 256 + tid;
            int r = idx >> 4, c = idx & 15;
            size_t goff = (size_t)(row0 + r) * D + c * 8;
            uint32_t soff = (r * ASTRIDE + c * 8) * 2;
            cp_async16(sbase + sab + soff, A + goff);
        }
        CP_COMMIT();
    };

    int t = blockIdx.x;
    int parity = 0;
    if (t < numTiles) stage(t, 0);
    for (; t < numTiles; t += gridDim.x, parity ^= 1) {
        int nxt = t + gridDim.x;
        if (nxt < numTiles) { stage(nxt, parity ^ 1); cp_wait<1>(); }
        else cp_wait<0>();
        __syncthreads();

        uint32_t a0 = sbase + ((parity ? H_SA1 : H_SA0) * 2) + aRel;
        uint32_t a1 = a0 + 16 * (ASTRIDE * 2);
        int row0 = t * TM;

        float acc[2][4][4];
        #pragma unroll
        for (int mt = 0; mt < 2; mt++)
            #pragma unroll
            for (int nt = 0; nt < 4; nt++)
                #pragma unroll
                for (int q = 0; q < 4; q++) acc[mt][nt][q] = 0.0f;

        #pragma unroll
        for (int ks = 0; ks < 8; ks++) {
            uint32_t koffB = (uint32_t)(ks * 32);
            uint32_t af[2][4];
            ldsm4(af[0], a0 + koffB);
            ldsm4(af[1], a1 + koffB);
            uint32_t bh[4][2], bl[4][2];
            #pragma unroll
            for (int np = 0; np < 2; np++) {
                uint32_t r4[4];
                ldsm4(r4, bHiBase + (uint32_t)(np * 16 * ASTRIDE * 2) + koffB);
                bh[2 * np][0] = r4[0]; bh[2 * np][1] = r4[1];
                bh[2 * np + 1][0] = r4[2]; bh[2 * np + 1][1] = r4[3];
                ldsm4(r4, bLoBase + (uint32_t)(np * 16 * ASTRIDE * 2) + koffB);
                bl[2 * np][0] = r4[0]; bl[2 * np][1] = r4[1];
                bl[2 * np + 1][0] = r4[2]; bl[2 * np + 1][1] = r4[3];
            }
            #pragma unroll
            for (int mt = 0; mt < 2; mt++)
                #pragma unroll
                for (int nt = 0; nt < 4; nt++) {
                    mma_f16(acc[mt][nt], af[mt], bh[nt]);
                    mma_f16(acc[mt][nt], af[mt], bl[nt]);
                }
        }

        int cbase = ncol0 + ((lane & 3) << 1);
        int rbase = row0 + mrow0 + (lane >> 2);
        #pragma unroll
        for (int mt = 0; mt < 2; mt++) {
            #pragma unroll
            for (int half = 0; half < 2; half++) {
                int gr = rbase + mt * 16 + half * 8;
                if (gr >= M) continue;
                __half* cp = Ch + (size_t)gr * D;
                #pragma unroll
                for (int nt = 0; nt < 4; nt++) {
                    int col = cbase + nt * 8;
                    __half2 hp = __floats2half2_rn(acc[mt][nt][2 * half],
                                                   acc[mt][nt][2 * half + 1]);
                    *(uint32_t*)(cp + col) = *(uint32_t*)&hp;
                }
            }
        }
        __syncthreads();
    }
}

// ================= bf16 3-pass GEMM (link predictor) =================
#define B_SAHI 0
#define B_SALO ABUF
#define B_SWH (2 * ABUF)
#define B_SWL (2 * ABUF + WBUF)
#define B_ELEMS (2 * ABUF + 2 * WBUF)
#define B_SMEM_BYTES (B_ELEMS * 2 + (512 + 256 + 8) * 4)

__global__ void __launch_bounds__(256, 2)
gemm_bf16_kernel(const __nv_bfloat16* __restrict__ Ahi, const __nv_bfloat16* __restrict__ Alo,
                 const float* __restrict__ embf, const int* __restrict__ tedg,
                 const __nv_bfloat16* __restrict__ Wt_hi, const __nv_bfloat16* __restrict__ Wt_lo,
                 const float* __restrict__ bias,
                 __nv_bfloat16* __restrict__ OutHi, __nv_bfloat16* __restrict__ OutLo,
                 const float* __restrict__ P3, const float* __restrict__ pb3,
                 float* __restrict__ outF,
                 int M, int numTiles, int stagemode, int epimode) {
    extern __shared__ __nv_bfloat16 sm[];
    uint32_t sbase = smem_u32(sm);
    float* fpart = (float*)(sm + B_ELEMS);
    float* fP3 = fpart + 512;
    float* fpb3 = fP3 + 256;
    int tid = threadIdx.x, wid = tid >> 5, lane = tid & 31;

    {
        const uint4* wh = (const uint4*)Wt_hi;
        const uint4* wl = (const uint4*)Wt_lo;
        for (int i = tid; i < 2048; i += 256) {
            int r = i >> 4, c = i & 15;
            *(uint4*)(sm + B_SWH + r * ASTRIDE + c * 8) = wh[i];
            *(uint4*)(sm + B_SWL + r * ASTRIDE + c * 8) = wl[i];
        }
        if (epimode == 2) {
            fP3[tid] = P3[tid];
            if (tid < 2) fpb3[tid] = pb3[tid];
        }
    }

    int mwid = wid >> 2;
    int nwid = wid & 3;
    int mrow0 = mwid << 5;
    int ncol0 = nwid << 5;

    uint32_t aRel = (uint32_t)(mrow0 + (lane & 15)) * (ASTRIDE * 2)
                  + (uint32_t)(((lane >> 4) << 3) * 2);
    uint32_t aHi0 = sbase + (B_SAHI * 2) + aRel;
    uint32_t aHi1 = aHi0 + 16 * (ASTRIDE * 2);
    uint32_t aLo0 = aHi0 + ABUF * 2;
    uint32_t aLo1 = aHi1 + ABUF * 2;

    uint32_t bN = (uint32_t)(ncol0 + ((lane >> 4) << 3) + (lane & 7));
    uint32_t bKB = (uint32_t)((((lane >> 3) & 1) << 3) * 2);
    uint32_t bHiBase = sbase + (B_SWH * 2) + bN * (ASTRIDE * 2) + bKB;
    uint32_t bLoBase = bHiBase + WBUF * 2;

    for (int t = blockIdx.x; t < numTiles; t += gridDim.x) {
        int row0 = t * TM;

        if (stagemode == 0) {
            #pragma unroll
            for (int it = 0; it < 4; it++) {
                int idx = it * 256 + tid;
                int r = idx >> 4, c = idx & 15;
                size_t goff = (size_t)(row0 + r) * D + c * 8;
                uint32_t soff = (r * ASTRIDE + c * 8) * 2;
                cp_async16(sbase + (B_SAHI * 2) + soff, Ahi + goff);
                cp_async16(sbase + (B_SALO * 2) + soff, Alo + goff);
            }
            CP_COMMIT();
            cp_wait<0>();
        } else {
            #pragma unroll
            for (int it = 0; it < 8; it++) {
                int idx = it * 256 + tid;
                int r = idx >> 5;
                int c4 = idx & 31;
                int grow = row0 + r;
                float4 v;
                if (grow < M) {
                    int s = tedg[2 * grow];
                    int d = tedg[2 * grow + 1];
                    float4 a = *(const float4*)(embf + (size_t)s * D + c4 * 4);
                    float4 b = *(const float4*)(embf + (size_t)d * D + c4 * 4);
                    v = make_float4(a.x * b.x, a.y * b.y, a.z * b.z, a.w * b.w);
                } else {
                    v = make_float4(0.f, 0.f, 0.f, 0.f);
                }
                uint2 hp, lp;
                split2b(v.x, v.y, hp.x, lp.x);
                split2b(v.z, v.w, hp.y, lp.y);
                *(uint2*)(sm + B_SAHI + r * ASTRIDE + c4 * 4) = hp;
                *(uint2*)(sm + B_SALO + r * ASTRIDE + c4 * 4) = lp;
            }
        }
        __syncthreads();

        float acc[2][4][4];
        #pragma unroll
        for (int mt = 0; mt < 2; mt++)
            #pragma unroll
            for (int nt = 0; nt < 4; nt++)
                #pragma unroll
                for (int q = 0; q < 4; q++) acc[mt][nt][q] = 0.0f;

        #pragma unroll
        for (int ks = 0; ks < 8; ks++) {
            uint32_t koffB = (uint32_t)(ks * 32);
            uint32_t ah[2][4], al[2][4];
            ldsm4(ah[0], aHi0 + koffB);
            ldsm4(ah[1], aHi1 + koffB);
            ldsm4(al[0], aLo0 + koffB);
            ldsm4(al[1], aLo1 + koffB);
            uint32_t bh[4][2], bl[4][2];
            #pragma unroll
            for (int np = 0; np < 2; np++) {
                uint32_t r4[4];
                ldsm4(r4, bHiBase + (uint32_t)(np * 16 * ASTRIDE * 2) + koffB);
                bh[2 * np][0] = r4[0]; bh[2 * np][1] = r4[1];
                bh[2 * np + 1][0] = r4[2]; bh[2 * np + 1][1] = r4[3];
                ldsm4(r4, bLoBase + (uint32_t)(np * 16 * ASTRIDE * 2) + koffB);
                bl[2 * np][0] = r4[0]; bl[2 * np][1] = r4[1];
                bl[2 * np + 1][0] = r4[2]; bl[2 * np + 1][1] = r4[3];
            }
            #pragma unroll
            for (int mt = 0; mt < 2; mt++)
                #pragma unroll
                for (int nt = 0; nt < 4; nt++) {
                    mma_bf16(acc[mt][nt], ah[mt], bh[nt]);
                    mma_bf16(acc[mt][nt], ah[mt], bl[nt]);
                    mma_bf16(acc[mt][nt], al[mt], bh[nt]);
                }
        }

        int cbase = ncol0 + ((lane & 3) << 1);

        if (epimode == 2) {
            float q0a[4], q1a[4];
            #pragma unroll
            for (int mt = 0; mt < 2; mt++) {
                #pragma unroll
                for (int half = 0; half < 2; half++) {
                    float q0 = 0.f, q1 = 0.f;
                    #pragma unroll
                    for (int nt = 0; nt < 4; nt++) {
                        int col = cbase + nt * 8;
                        float z0 = fmaxf(acc[mt][nt][2 * half] + bias[col], 0.f);
                        float z1 = fmaxf(acc[mt][nt][2 * half + 1] + bias[col + 1], 0.f);
                        q0 += z0 * fP3[2 * col] + z1 * fP3[2 * (col + 1)];
                        q1 += z0 * fP3[2 * col + 1] + z1 * fP3[2 * (col + 1) + 1];
                    }
                    q0 += __shfl_xor_sync(0xFFFFFFFFu, q0, 1);
                    q0 += __shfl_xor_sync(0xFFFFFFFFu, q0, 2);
                    q1 += __shfl_xor_sync(0xFFFFFFFFu, q1, 1);
                    q1 += __shfl_xor_sync(0xFFFFFFFFu, q1, 2);
                    q0a[mt * 2 + half] = q0;
                    q1a[mt * 2 + half] = q1;
                    if (nwid != 0 && (lane & 3) == 0) {
                        int rl = mrow0 + mt * 16 + half * 8 + (lane >> 2);
                        fpart[rl * 8 + nwid * 2]     = q0;
                        fpart[rl * 8 + nwid * 2 + 1] = q1;
                    }
                }
            }
            __syncthreads();
            if (nwid == 0 && (lane & 3) == 0) {
                #pragma unroll
                for (int mt = 0; mt < 2; mt++) {
                    #pragma unroll
                    for (int half = 0; half < 2; half++) {
                        int rl = mrow0 + mt * 16 + half * 8 + (lane >> 2);
                        int gr = row0 + rl;
                        if (gr < M) {
                            float z0 = q0a[mt * 2 + half] + fpb3[0];
                            float z1 = q1a[mt * 2 + half] + fpb3[1];
                            #pragma unroll
                            for (int nw = 1; nw < 4; nw++) {
                                z0 += fpart[rl * 8 + nw * 2];
                                z1 += fpart[rl * 8 + nw * 2 + 1];
                            }
                            float nrm = fmaxf(sqrtf(z0 * z0 + z1 * z1), 1e-12f);
                            z0 /= nrm; z1 /= nrm;
                            float mm = fmaxf(z0, z1);
                            float lse = mm + logf(expf(z0 - mm) + expf(z1 - mm));
                            outF[2 * gr]     = z0 - lse;
                            outF[2 * gr + 1] = z1 - lse;
                        }
                    }
                }
            }
        } else {
            int rbase = row0 + mrow0 + (lane >> 2);
            #pragma unroll
            for (int mt = 0; mt < 2; mt++) {
                #pragma unroll
                for (int half = 0; half < 2; half++) {
                    int gr = rbase + mt * 16 + half * 8;
                    if (gr >= M) continue;
                    #pragma unroll
                    for (int nt = 0; nt < 4; nt++) {
                        int col = cbase + nt * 8;
                        float o0 = fmaxf(acc[mt][nt][2 * half] + bias[col], 0.f);
                        float o1 = fmaxf(acc[mt][nt][2 * half + 1] + bias[col + 1], 0.f);
                        uint32_t hp, lp;
                        split2b(o0, o1, hp, lp);
                        *(uint32_t*)(OutHi + (size_t)gr * D + col) = hp;
                        *(uint32_t*)(OutLo + (size_t)gr * D + col) = lp;
                    }
                }
            }
        }
        __syncthreads();
    }
}

// ---------------- aggregation: 2 dsts per warp, 16 lanes x uint4 per dst ----------------
__global__ void agg_kernel(const __half* __restrict__ H, const int* __restrict__ rowptr,
                           const int* __restrict__ eidx, const float* __restrict__ bias,
                           __half* __restrict__ OutH, float* __restrict__ OutF,
                           int relu, int outmode, int N) {
    int gw = (blockIdx.x * blockDim.x + threadIdx.x) >> 5;
    int lane = threadIdx.x & 31;
    int half = lane >> 4;
    int l16 = lane & 15;
    int d = gw * 2 + half;
    if (d >= N) return;
    int coff = l16 << 3;                          // 8 halves = 16 B per lane
    int beg = rowptr[d], end = rowptr[d + 1];
    float acc[8];
    #pragma unroll
    for (int q = 0; q < 8; q++) acc[q] = 0.f;

    int j = beg;
    #pragma unroll 1
    for (; j + 4 <= end; j += 4) {
        int s0 = eidx[j], s1 = eidx[j + 1], s2 = eidx[j + 2], s3 = eidx[j + 3];
        uint4 r0 = *(const uint4*)(H + (size_t)s0 * D + coff);
        uint4 r1 = *(const uint4*)(H + (size_t)s1 * D + coff);
        uint4 r2 = *(const uint4*)(H + (size_t)s2 * D + coff);
        uint4 r3 = *(const uint4*)(H + (size_t)s3 * D + coff);
        const uint4 rr[4] = {r0, r1, r2, r3};
        #pragma unroll
        for (int u = 0; u < 4; u++) {
            float2 f0 = __half22float2(*(__half2*)&rr[u].x);
            float2 f1 = __half22float2(*(__half2*)&rr[u].y);
            float2 f2 = __half22float2(*(__half2*)&rr[u].z);
            float2 f3 = __half22float2(*(__half2*)&rr[u].w);
            acc[0] += f0.x; acc[1] += f0.y; acc[2] += f1.x; acc[3] += f1.y;
            acc[4] += f2.x; acc[5] += f2.y; acc[6] += f3.x; acc[7] += f3.y;
        }
    }
    for (; j < end; j++) {
        int s = eidx[j];
        uint4 r = *(const uint4*)(H + (size_t)s * D + coff);
        float2 f0 = __half22float2(*(__half2*)&r.x);
        float2 f1 = __half22float2(*(__half2*)&r.y);
        float2 f2 = __half22float2(*(__half2*)&r.z);
        float2 f3 = __half22float2(*(__half2*)&r.w);
        acc[0] += f0.x; acc[1] += f0.y; acc[2] += f1.x; acc[3] += f1.y;
        acc[4] += f2.x; acc[5] += f2.y; acc[6] += f3.x; acc[7] += f3.y;
    }

    float4 b0 = *(const float4*)(bias + coff);
    float4 b1 = *(const float4*)(bias + coff + 4);
    acc[0] += b0.x; acc[1] += b0.y; acc[2] += b0.z; acc[3] += b0.w;
    acc[4] += b1.x; acc[5] += b1.y; acc[6] += b1.z; acc[7] += b1.w;
    if (relu) {
        #pragma unroll
        for (int q = 0; q < 8; q++) acc[q] = fmaxf(acc[q], 0.f);
    }
    if (outmode == 0) {
        __half2 h0 = __floats2half2_rn(acc[0], acc[1]);
        __half2 h1 = __floats2half2_rn(acc[2], acc[3]);
        __half2 h2 = __floats2half2_rn(acc[4], acc[5]);
        __half2 h3 = __floats2half2_rn(acc[6], acc[7]);
        uint4 p;
        p.x = *(uint32_t*)&h0; p.y = *(uint32_t*)&h1;
        p.z = *(uint32_t*)&h2; p.w = *(uint32_t*)&h3;
        *(uint4*)(OutH + (size_t)d * D + coff) = p;
    } else {
        *(float4*)(OutF + (size_t)d * D + coff)     = make_float4(acc[0], acc[1], acc[2], acc[3]);
        *(float4*)(OutF + (size_t)d * D + coff + 4) = make_float4(acc[4], acc[5], acc[6], acc[7]);
    }
}

// ---------------- launch ----------------
extern "C" void kernel_launch(void* const* d_in, const int* in_sizes, int n_in,
                              void* d_out, int out_size) {
    const float* x    = (const float*)d_in[0];
    const int*   adj  = (const int*)d_in[1];
    const int*   tedg = (const int*)d_in[2];
    const float* W1 = (const float*)d_in[3];  const float* b1  = (const float*)d_in[4];
    const float* W2 = (const float*)d_in[5];  const float* b2  = (const float*)d_in[6];
    const float* W3 = (const float*)d_in[7];  const float* b3  = (const float*)d_in[8];
    const float* P1 = (const float*)d_in[9];  const float* pb1 = (const float*)d_in[10];
    const float* P2 = (const float*)d_in[11]; const float* pb2 = (const float*)d_in[12];
    const float* P3 = (const float*)d_in[13]; const float* pb3 = (const float*)d_in[14];
    float* out = (float*)d_out;

    int N  = in_sizes[0] / D;
    int E  = in_sizes[1] / 2;
    int NE = in_sizes[2] / 2;

    cudaFuncSetAttribute((const void*)gemm_f16_kernel,
                         cudaFuncAttributeMaxDynamicSharedMemorySize, H_SMEM_BYTES);
    cudaFuncSetAttribute((const void*)gemm_bf16_kernel,
                         cudaFuncAttributeMaxDynamicSharedMemorySize, B_SMEM_BYTES);

    __nv_bfloat16 *Ahi, *Alo, *Whi, *Wlo;
    __half* Hh;
    float* emb;
    int *deg, *rowptr, *cur, *eidx, *bsum;
    cudaGetSymbolAddress((void**)&Ahi, g_Ahi);
    cudaGetSymbolAddress((void**)&Alo, g_Alo);
    cudaGetSymbolAddress((void**)&Hh,  g_Hh);
    cudaGetSymbolAddress((void**)&emb, g_emb);
    cudaGetSymbolAddress((void**)&deg,    g_deg);
    cudaGetSymbolAddress((void**)&rowptr, g_rowptr);
    cudaGetSymbolAddress((void**)&cur,    g_cur);
    cudaGetSymbolAddress((void**)&eidx,   g_eidx);
    cudaGetSymbolAddress((void**)&bsum,   g_bsum);
    cudaGetSymbolAddress((void**)&Whi,  g_Whi);
    cudaGetSymbolAddress((void**)&Wlo,  g_Wlo);

    __half* Ah16 = (__half*)Ahi;
    const __half* Wh16 = (const __half*)Whi;
    const __half* Wl16 = (const __half*)Wlo;

    const int* src = adj;
    const int* dst = adj + E;

    int nScanBlk = (N + 1023) / 1024;
    int tilesN  = (N + TM - 1) / TM;
    int tilesNE = (NE + TM - 1) / TM;
    int gN  = tilesN  < 296 ? tilesN  : 296;
    int gNE = tilesNE < 296 ? tilesNE : 296;
    int nWarp = (N + 1) / 2;
    int aggBlk = (nWarp * 32 + 255) / 256;

    // ---- fused setup (weights + xsplit + deg zero) + L1 GEMM, CSR chain after ----
    setup_kernel<<<1184, 256>>>(W1, W2, W3, P1, P2, Whi, Wlo, x, Ah16, deg, N);
    gemm_f16_kernel<<<gN, 256, H_SMEM_BYTES>>>(Ah16, Wh16, Wl16, Hh, N, tilesN);
    hist_kernel<<<(E + 255) / 256, 256>>>(dst, E, deg);
    scan1_kernel<<<nScanBlk, 1024>>>(deg, rowptr, bsum, N);
    scan2_kernel<<<1, 32>>>(bsum, nScanBlk);
    scan3_kernel<<<nScanBlk, 1024>>>(deg, rowptr, cur, bsum, N);
    fill_csr_kernel<<<(E + 255) / 256, 256>>>(src, dst, E, cur, eidx);

    // ---- trunk ----
    agg_kernel<<<aggBlk, 256>>>(Hh, rowptr, eidx, b1, Ah16, nullptr, 1, 0, N);
    gemm_f16_kernel<<<gN, 256, H_SMEM_BYTES>>>(Ah16, Wh16 + 16384, Wl16 + 16384, Hh, N, tilesN);
    agg_kernel<<<aggBlk, 256>>>(Hh, rowptr, eidx, b2, Ah16, nullptr, 1, 0, N);
    gemm_f16_kernel<<<gN, 256, H_SMEM_BYTES>>>(Ah16, Wh16 + 2 * 16384, Wl16 + 2 * 16384, Hh, N, tilesN);
    agg_kernel<<<aggBlk, 256>>>(Hh, rowptr, eidx, b3, nullptr, emb, 0, 1, N);

    // ---- link predictor (bf16 3-pass) ----
    gemm_bf16_kernel<<<gNE, 256, B_SMEM_BYTES>>>(nullptr, nullptr, emb, tedg,
        Whi + 3 * 16384, Wlo + 3 * 16384, pb1, Ahi, Alo, nullptr, nullptr, nullptr,
        NE, tilesNE, 1, 1);
    gemm_bf16_kernel<<<gNE, 256, B_SMEM_BYTES>>>(Ahi, Alo, nullptr, nullptr,
        Whi + 4 * 16384, Wlo + 4 * 16384, pb2, nullptr, nullptr, P3, pb3, out,
        NE, tilesNE, 0, 2);
}